// round 10
// baseline (speedup 1.0000x reference)
#include <cuda_runtime.h>
#include <cuda_fp16.h>

// Problem constants (fixed by setup_inputs)
#define T_LEN    131072
#define K_WIN    31
#define HALO     15
#define WTILE    512          // elements per 1-warp block; T_LEN/WTILE = 256
#define CHUNK    16           // consecutive elements per thread (sliding window)
#define EPS      1e-6f
#define KURT_MAX 20.0f

// ---- small helpers ----------------------------------------------------------
__device__ __forceinline__ unsigned tf32_of(float x) {
    unsigned u; asm("cvt.rna.tf32.f32 %0, %1;" : "=r"(u) : "f"(x)); return u;
}
// pack two f32 into half2: low half = lo, high half = hi  (cvt d,a,b -> hi=a, lo=b)
__device__ __forceinline__ unsigned h2_of(float lo, float hi) {
    unsigned r; asm("cvt.rn.f16x2.f32 %0, %1, %2;" : "=r"(r) : "f"(hi), "f"(lo)); return r;
}
__device__ __forceinline__ unsigned hmax2_zero(unsigned a) {
    unsigned r; asm("max.f16x2 %0, %1, %2;" : "=r"(r) : "r"(a), "r"(0u)); return r;
}

// mma.m16n8k8 row.col f32.tf32.tf32.f32 : D += A*B (acc in place)
__device__ __forceinline__ void mma_tf32(float& c0, float& c1, float& c2, float& c3,
                                         unsigned a0, unsigned a1, unsigned a2, unsigned a3,
                                         unsigned b0, unsigned b1) {
    asm volatile("mma.sync.aligned.m16n8k8.row.col.f32.tf32.tf32.f32 "
                 "{%0,%1,%2,%3}, {%4,%5,%6,%7}, {%8,%9}, {%0,%1,%2,%3};"
                 : "+f"(c0), "+f"(c1), "+f"(c2), "+f"(c3)
                 : "r"(a0), "r"(a1), "r"(a2), "r"(a3), "r"(b0), "r"(b1));
}
// mma.m16n8k16 row.col f32.f16.f16.f32 : D += A*B
__device__ __forceinline__ void mma_f16(float& c0, float& c1, float& c2, float& c3,
                                        unsigned a0, unsigned a1, unsigned a2, unsigned a3,
                                        unsigned b0, unsigned b1) {
    asm volatile("mma.sync.aligned.m16n8k16.row.col.f32.f16.f16.f32 "
                 "{%0,%1,%2,%3}, {%4,%5,%6,%7}, {%8,%9}, {%0,%1,%2,%3};"
                 : "+f"(c0), "+f"(c1), "+f"(c2), "+f"(c3)
                 : "r"(a0), "r"(a1), "r"(a2), "r"(a3), "r"(b0), "r"(b1));
}

// 6 features for one element + slide window sums forward.
__device__ __forceinline__ void feat_step(
    const float* __restrict__ xs, int idx, int t,
    float &S1, float &S2, float &S3, float &S4,
    float &f0, float &f1, float &f2, float &f3, float &f4, float &f5)
{
    const float INV31 = 1.0f / 31.0f;
    float mu = S1 * INV31;
    float m2 = S2 * INV31;
    float m3 = S3 * INV31;
    float m4 = S4 * INV31;
    float mu2 = mu * mu;
    float var = m2 - mu2 + EPS;
    float m4c = m4 - 4.0f * mu * m3 + 6.0f * mu2 * m2 - 3.0f * mu2 * mu2;
    float kurt = fminf(__fdividef(m4c, var * var), KURT_MAX);

    float x  = xs[idx + 15];
    float xm = xs[idx + 14];
    float xp = xs[idx + 16];
    float d1 = fabsf(x - xm);                 // clamp staging makes d1[0]==0
    float d2 = fabsf(xp - 2.0f * x + xm);
    if (t == 0 || t == T_LEN - 1) d2 = 0.0f;

    f0 = x; f1 = d1; f2 = d2; f3 = mu; f4 = var; f5 = kurt;

    float xa = xs[idx + 31];
    float xr = xs[idx];
    float xa2 = xa * xa, xr2 = xr * xr;
    S1 += xa - xr;
    S2 += xa2 - xr2;
    S3 += xa2 * xa - xr2 * xr;
    S4 += xa2 * xa2 - xr2 * xr2;
}

// One warp per block. Warp handles WTILE=512 contiguous elements of one row.
__global__ __launch_bounds__(32, 12)
void gate_router_mma(const float* __restrict__ s,
                     const float* __restrict__ W1, const float* __restrict__ b1,
                     const float* __restrict__ W2, const float* __restrict__ b2,
                     float* __restrict__ out)
{
    __shared__ float xs[WTILE + 2 * HALO + 2];            // 544 floats
    // Feature staging: 512 elems x 8 tf32 words (column-permuted for A-frag LDS.64).
    // Tile j's region ([j*128, j*128+128) words) is REUSED as logit staging
    // (48 words, output-ordered) after tile j's A fragments are consumed.
    __shared__ __align__(16) float feat[WTILE * 8];       // 16 KB

    const int lane = threadIdx.x;
    const int g  = lane >> 2;       // 0..7  (fragment group = row)
    const int tq = lane & 3;        // 0..3  (thread-in-group)
    const int wbase = blockIdx.x * WTILE;                 // elem offset within row
    const int row = blockIdx.y;
    const float* __restrict__ srow = s + (long long)row * T_LEN;

    // ---- stage signal + halo (clamp == replicate padding) ------------------
    for (int i = lane; i < WTILE + 2 * HALO + 2; i += 32) {
        int gg = wbase - HALO + i;
        gg = max(0, min(T_LEN - 1, gg));
        xs[i] = srow[gg];
    }

    // ---- constant fragments (registers) ------------------------------------
    // GEMM1 B (tf32): b0=(k=tq, n), b1=(k=tq+4, n); n = ni*8 + g.
    // W1eff rows: 0..5 = W1, 6 = b1 (bias folded; feature col 6 == 1.0), 7 = 0.
    unsigned B1[4][2];
    #pragma unroll
    for (int ni = 0; ni < 4; ++ni) {
        int n = ni * 8 + g;
        B1[ni][0] = tf32_of(W1[tq * 32 + n]);             // k = tq in 0..3
        int k2 = tq + 4;                                  // 4..7
        float v = (k2 < 6) ? W1[k2 * 32 + n] : (k2 == 6 ? b1[n] : 0.0f);
        B1[ni][1] = tf32_of(v);
    }
    // GEMM2 B (f16): per kp piece, b0 = h2(k=16kp+2tq, +1; col n=g), b1 = rows +8,+9.
    // W2eff[j][c] = c<3 ? W2[j*3+c] : 0  (n = g; cols >= 3 are padding).
    unsigned B2[2][2];
    #pragma unroll
    for (int kp = 0; kp < 2; ++kp) {
        int j0 = kp * 16 + 2 * tq;
        float w00 = (g < 3) ? W2[(j0    ) * 3 + g] : 0.0f;
        float w01 = (g < 3) ? W2[(j0 + 1) * 3 + g] : 0.0f;
        float w10 = (g < 3) ? W2[(j0 + 8) * 3 + g] : 0.0f;
        float w11 = (g < 3) ? W2[(j0 + 9) * 3 + g] : 0.0f;
        B2[kp][0] = h2_of(w00, w01);
        B2[kp][1] = h2_of(w10, w11);
    }
    // C2 bias init for this thread's D columns (2tq, 2tq+1)
    float cI0 = (2 * tq     < 3) ? b2[2 * tq]     : 0.0f;
    float cI1 = (2 * tq + 1 < 3) ? b2[2 * tq + 1] : 0.0f;

    __syncthreads();   // xs visible

    // ---- features: thread owns 16 consecutive elems, sliding 31-window -----
    const int base = lane * CHUNK;            // xs index of (t0 - 15)
    float S1 = 0.f, S2 = 0.f, S3 = 0.f, S4 = 0.f;
    #pragma unroll
    for (int k = 0; k < K_WIN; ++k) {
        float v = xs[base + k];
        float v2 = v * v;
        S1 += v; S2 += v2; S3 += v2 * v; S4 += v2 * v2;
    }
    const int t0 = wbase + base;

    // permuted column order pos(c) = 2*(c%4) + c/4 :
    //   buffer = [f0, f4, f1, f5, f2, 1.0, f3, 0] -> A-frag (cols tq, tq+4) = LDS.64 @ 2tq
    const unsigned ONE_TF32 = 0x3F800000u;
    #pragma unroll
    for (int e = 0; e < CHUNK; ++e) {
        float f0, f1, f2, f3, f4, f5;
        feat_step(xs, base + e, t0 + e, S1, S2, S3, S4, f0, f1, f2, f3, f4, f5);
        unsigned* fb = reinterpret_cast<unsigned*>(&feat[(base + e) * 8]);
        uint4 v0 = make_uint4(tf32_of(f0), tf32_of(f4), tf32_of(f1), tf32_of(f5));
        uint4 v1 = make_uint4(tf32_of(f2), ONE_TF32, tf32_of(f3), 0u);
        reinterpret_cast<uint4*>(fb)[0] = v0;
        reinterpret_cast<uint4*>(fb)[1] = v1;
    }
    __syncwarp();

    // ---- 32 tiles of 16 elements: GEMM1(tf32) -> relu/cvt -> GEMM2(f16) ----
    #pragma unroll 2
    for (int j = 0; j < 32; ++j) {
        int eg = j * 16 + g;
        // A1 fragments: row eg -> (a0, a2) = (col tq, col tq+4); row eg+8 -> (a1, a3)
        uint2 lo = *reinterpret_cast<const uint2*>(&feat[eg * 8 + 2 * tq]);
        uint2 hi = *reinterpret_cast<const uint2*>(&feat[(eg + 8) * 8 + 2 * tq]);

        float c0[4], c1[4], c2[4], c3[4];     // per ni piece (hidden cols 8ni+2tq, +1)
        #pragma unroll
        for (int ni = 0; ni < 4; ++ni) {
            c0[ni] = 0.f; c1[ni] = 0.f; c2[ni] = 0.f; c3[ni] = 0.f;
            mma_tf32(c0[ni], c1[ni], c2[ni], c3[ni],
                     lo.x, hi.x, lo.y, hi.y, B1[ni][0], B1[ni][1]);
        }

        // relu + cvt: C frags == f16 A-frag layout of m16n8k16 (register chaining)
        unsigned A2[2][4];
        #pragma unroll
        for (int ni = 0; ni < 4; ++ni) {
            unsigned p0 = hmax2_zero(h2_of(c0[ni], c1[ni]));   // row g,   k=8ni+2tq,+1
            unsigned p1 = hmax2_zero(h2_of(c2[ni], c3[ni]));   // row g+8
            A2[ni >> 1][(ni & 1) ? 2 : 0] = p0;
            A2[ni >> 1][(ni & 1) ? 3 : 1] = p1;
        }

        float d0 = cI0, d1 = cI1, d2 = cI0, d3 = cI1;
        mma_f16(d0, d1, d2, d3, A2[0][0], A2[0][1], A2[0][2], A2[0][3], B2[0][0], B2[0][1]);
        mma_f16(d0, d1, d2, d3, A2[1][0], A2[1][1], A2[1][2], A2[1][3], B2[1][0], B2[1][1]);

        // WAR guard: every lane's A-loads of tile j must complete before any
        // lane overwrites tile j's region with logits (ITS divergence safety).
        __syncwarp();

        // stash logits output-ordered into tile j's dead region: [j*128 + r*3 + c]
        int rb = j * 128;
        if (tq == 0) {                        // D cols 0,1
            feat[rb + g * 3]           = d0;
            feat[rb + g * 3 + 1]       = d1;
            feat[rb + (g + 8) * 3]     = d2;
            feat[rb + (g + 8) * 3 + 1] = d3;
        } else if (tq == 1) {                 // D col 2 (col 3 = pad, discarded)
            feat[rb + g * 3 + 2]       = d0;
            feat[rb + (g + 8) * 3 + 2] = d2;
        }
    }
    __syncwarp();

    // ---- coalesced writeout: 1536 floats = 384 float4, lane-strided --------
    // Within tile j, smem words [j*128, j*128+48) are already output-ordered,
    // mapping to out words [j*48, j*48+48).  float4 q: tile = q/12, word 4*(q%12).
    float* __restrict__ orow = out + ((long long)row * T_LEN + wbase) * 3;
    float4* __restrict__ o4 = reinterpret_cast<float4*>(orow);
    #pragma unroll
    for (int q = lane; q < 384; q += 32) {
        int j = q / 12;
        int w = (q - j * 12) * 4;
        o4[q] = *reinterpret_cast<const float4*>(&feat[j * 128 + w]);
    }
}

extern "C" void kernel_launch(void* const* d_in, const int* in_sizes, int n_in,
                              void* d_out, int out_size)
{
    const float* s  = (const float*)d_in[0];   // [B*T]
    const float* W1 = (const float*)d_in[1];   // [6*32]
    const float* b1 = (const float*)d_in[2];   // [32]
    const float* W2 = (const float*)d_in[3];   // [32*3]
    const float* b2 = (const float*)d_in[4];   // [3]
    float* out = (float*)d_out;                // [B*T*3]

    int B = in_sizes[0] / T_LEN;
    dim3 grid(T_LEN / WTILE, B);
    gate_router_mma<<<grid, 32>>>(s, W1, b1, W2, b2, out);
}

// round 11
// speedup vs baseline: 1.9759x; 1.9759x over previous
#include <cuda_runtime.h>
#include <cuda_fp16.h>

// Problem constants (fixed by setup_inputs)
#define T_LEN    131072
#define K_WIN    31
#define HALO     15
#define WTILE    512          // elements per 1-warp block; T_LEN/WTILE = 256
#define CHUNK    16           // consecutive elements per thread (sliding window)
#define TPITCH   272          // bytes per 16-element tile in feat buffer (17*16: conflict-free)
#define EPS      1e-6f
#define KURT_MAX 20.0f

// ---- small helpers ----------------------------------------------------------
// pack two f32 into f16x2: low half = lo, high half = hi (cvt d,a,b -> hi=a, lo=b)
__device__ __forceinline__ unsigned h2_of(float lo, float hi) {
    unsigned r; asm("cvt.rn.f16x2.f32 %0, %1, %2;" : "=r"(r) : "f"(hi), "f"(lo)); return r;
}
__device__ __forceinline__ unsigned hmax2_zero(unsigned a) {
    unsigned r; asm("max.f16x2 %0, %1, %2;" : "=r"(r) : "r"(a), "r"(0u)); return r;
}

// mma.m16n8k8 row.col f32.f16.f16.f32 : D += A*B (acc in place)
__device__ __forceinline__ void mma_f16k8(float& c0, float& c1, float& c2, float& c3,
                                          unsigned a0, unsigned a1, unsigned b0) {
    asm volatile("mma.sync.aligned.m16n8k8.row.col.f32.f16.f16.f32 "
                 "{%0,%1,%2,%3}, {%4,%5}, {%6}, {%0,%1,%2,%3};"
                 : "+f"(c0), "+f"(c1), "+f"(c2), "+f"(c3)
                 : "r"(a0), "r"(a1), "r"(b0));
}
// mma.m16n8k16 row.col f32.f16.f16.f32 : D += A*B
__device__ __forceinline__ void mma_f16(float& c0, float& c1, float& c2, float& c3,
                                        unsigned a0, unsigned a1, unsigned a2, unsigned a3,
                                        unsigned b0, unsigned b1) {
    asm volatile("mma.sync.aligned.m16n8k16.row.col.f32.f16.f16.f32 "
                 "{%0,%1,%2,%3}, {%4,%5,%6,%7}, {%8,%9}, {%0,%1,%2,%3};"
                 : "+f"(c0), "+f"(c1), "+f"(c2), "+f"(c3)
                 : "r"(a0), "r"(a1), "r"(a2), "r"(a3), "r"(b0), "r"(b1));
}

// 6 features for one element + slide window sums forward.
__device__ __forceinline__ void feat_step(
    const float* __restrict__ xs, int idx, int t,
    float &S1, float &S2, float &S3, float &S4,
    float &f0, float &f1, float &f2, float &f3, float &f4, float &f5)
{
    const float INV31 = 1.0f / 31.0f;
    float mu = S1 * INV31;
    float m2 = S2 * INV31;
    float m3 = S3 * INV31;
    float m4 = S4 * INV31;
    float mu2 = mu * mu;
    float var = m2 - mu2 + EPS;
    float m4c = m4 - 4.0f * mu * m3 + 6.0f * mu2 * m2 - 3.0f * mu2 * mu2;
    float kurt = fminf(__fdividef(m4c, var * var), KURT_MAX);

    float x  = xs[idx + 15];
    float xm = xs[idx + 14];
    float xp = xs[idx + 16];
    float d1 = fabsf(x - xm);                 // clamp staging makes d1[0]==0
    float d2 = fabsf(xp - 2.0f * x + xm);
    if (t == 0 || t == T_LEN - 1) d2 = 0.0f;

    f0 = x; f1 = d1; f2 = d2; f3 = mu; f4 = var; f5 = kurt;

    float xa = xs[idx + 31];
    float xr = xs[idx];
    float xa2 = xa * xa, xr2 = xr * xr;
    S1 += xa - xr;
    S2 += xa2 - xr2;
    S3 += xa2 * xa - xr2 * xr;
    S4 += xa2 * xa2 - xr2 * xr2;
}

// One warp per block. Warp handles WTILE=512 contiguous elements of one row.
__global__ __launch_bounds__(32, 18)
void gate_router_mma(const float* __restrict__ s,
                     const float* __restrict__ W1, const float* __restrict__ b1,
                     const float* __restrict__ W2, const float* __restrict__ b2,
                     float* __restrict__ out)
{
    __shared__ float xs[WTILE + 2 * HALO + 2];                 // 544 floats
    // Feature staging: 32 tiles x TPITCH bytes. Tile j holds 16 elems x 16B of
    // f16 features; after tile j's A-fragments are consumed, its region is
    // REUSED as f32 logit staging (48 words, output-ordered).
    __shared__ __align__(16) unsigned char featb[32 * TPITCH]; // 8704 B

    const int lane = threadIdx.x;
    const int g  = lane >> 2;       // 0..7  (fragment group = row)
    const int tq = lane & 3;        // 0..3  (thread-in-group)
    const int wbase = blockIdx.x * WTILE;
    const int row = blockIdx.y;
    const float* __restrict__ srow = s + (long long)row * T_LEN;

    // ---- stage signal + halo (clamp == replicate padding) ------------------
    for (int i = lane; i < WTILE + 2 * HALO + 2; i += 32) {
        int gg = wbase - HALO + i;
        gg = max(0, min(T_LEN - 1, gg));
        xs[i] = srow[gg];
    }

    // ---- constant fragments (registers) ------------------------------------
    // GEMM1 B (f16, m16n8k8): b = {W1eff[2tq][n] lo, W1eff[2tq+1][n] hi}, n = ni*8+g.
    // W1eff rows: 0..5 = W1, 6 = b1 (bias folded; feature 6 == 1.0), 7 = 0.
    unsigned B1[4];
    #pragma unroll
    for (int ni = 0; ni < 4; ++ni) {
        int n = ni * 8 + g;
        int k0 = 2 * tq, k1 = 2 * tq + 1;
        float wlo = (k0 < 6) ? W1[k0 * 32 + n] : b1[n];   // k0 in {0,2,4,6}
        float whi = (k1 < 6) ? W1[k1 * 32 + n] : 0.0f;    // k1 in {1,3,5,7}
        B1[ni] = h2_of(wlo, whi);
    }
    // GEMM2 B (f16, m16n8k16): per kp, b0 = {W2eff[16kp+2tq][g], [+1][g]}, b1 = rows +8,+9.
    unsigned B2[2][2];
    #pragma unroll
    for (int kp = 0; kp < 2; ++kp) {
        int j0 = kp * 16 + 2 * tq;
        float w00 = (g < 3) ? W2[(j0    ) * 3 + g] : 0.0f;
        float w01 = (g < 3) ? W2[(j0 + 1) * 3 + g] : 0.0f;
        float w10 = (g < 3) ? W2[(j0 + 8) * 3 + g] : 0.0f;
        float w11 = (g < 3) ? W2[(j0 + 9) * 3 + g] : 0.0f;
        B2[kp][0] = h2_of(w00, w01);
        B2[kp][1] = h2_of(w10, w11);
    }
    // C2 bias init for this thread's D columns (2tq, 2tq+1)
    float cI0 = (2 * tq     < 3) ? b2[2 * tq]     : 0.0f;
    float cI1 = (2 * tq + 1 < 3) ? b2[2 * tq + 1] : 0.0f;

    __syncthreads();   // xs visible

    // ---- features: thread owns 16 consecutive elems (= tile lane) ----------
    const int base = lane * CHUNK;            // xs index of (t0 - 15)
    float S1 = 0.f, S2 = 0.f, S3 = 0.f, S4 = 0.f;
    #pragma unroll
    for (int k = 0; k < K_WIN; ++k) {
        float v = xs[base + k];
        float v2 = v * v;
        S1 += v; S2 += v2; S3 += v2 * v; S4 += v2 * v2;
    }
    const int t0 = wbase + base;

    // f16 feature record per element: {f0,f1,f2,f3,f4,f5,1,0} = 4 words, STS.128.
    const unsigned ONE_ZERO = 0x00003C00u;    // lo = 1.0h (feature 6), hi = 0 (feature 7)
    unsigned char* myTile = featb + lane * TPITCH;
    #pragma unroll
    for (int e = 0; e < CHUNK; ++e) {
        float f0, f1, f2, f3, f4, f5;
        feat_step(xs, base + e, t0 + e, S1, S2, S3, S4, f0, f1, f2, f3, f4, f5);
        uint4 v;
        v.x = h2_of(f0, f1);
        v.y = h2_of(f2, f3);
        v.z = h2_of(f4, f5);
        v.w = ONE_ZERO;
        *reinterpret_cast<uint4*>(myTile + e * 16) = v;
    }
    __syncwarp();

    // ---- 32 tiles: GEMM1 (f16 k8) -> relu/pack -> GEMM2 (f16 k16) ----------
    #pragma unroll 4
    for (int j = 0; j < 32; ++j) {
        const unsigned char* tb = featb + j * TPITCH + g * 16 + tq * 4;
        unsigned a0 = *reinterpret_cast<const unsigned*>(tb);         // row j*16+g,  k=2tq,+1
        unsigned a1 = *reinterpret_cast<const unsigned*>(tb + 128);   // row j*16+g+8

        float c0[4], c1[4], c2[4], c3[4];     // hidden cols 8ni+2tq, +1; rows g, g+8
        #pragma unroll
        for (int ni = 0; ni < 4; ++ni) {
            c0[ni] = 0.f; c1[ni] = 0.f; c2[ni] = 0.f; c3[ni] = 0.f;
            mma_f16k8(c0[ni], c1[ni], c2[ni], c3[ni], a0, a1, B1[ni]);
        }

        // relu + pack: C frags == f16 A-frag layout of m16n8k16 (register chaining)
        unsigned A2[2][4];
        #pragma unroll
        for (int ni = 0; ni < 4; ++ni) {
            unsigned p0 = hmax2_zero(h2_of(c0[ni], c1[ni]));   // row g,   k=8ni+2tq,+1
            unsigned p1 = hmax2_zero(h2_of(c2[ni], c3[ni]));   // row g+8
            A2[ni >> 1][(ni & 1) ? 2 : 0] = p0;
            A2[ni >> 1][(ni & 1) ? 3 : 1] = p1;
        }

        float d0 = cI0, d1 = cI1, d2 = cI0, d3 = cI1;
        mma_f16(d0, d1, d2, d3, A2[0][0], A2[0][1], A2[0][2], A2[0][3], B2[0][0], B2[0][1]);
        mma_f16(d0, d1, d2, d3, A2[1][0], A2[1][1], A2[1][2], A2[1][3], B2[1][0], B2[1][1]);

        // No syncwarp needed: every lane's A-loads of tile j complete before the
        // warp-converging mma.sync (operand dependence), and these stores depend
        // on GEMM2 results -> WAR on tile j's region cannot occur.
        float* tb32 = reinterpret_cast<float*>(featb + j * TPITCH);
        if (tq == 0) {                        // D cols 0,1
            tb32[g * 3]           = d0;
            tb32[g * 3 + 1]       = d1;
            tb32[(g + 8) * 3]     = d2;
            tb32[(g + 8) * 3 + 1] = d3;
        } else if (tq == 1) {                 // D col 2 (col 3 = pad, discarded)
            tb32[g * 3 + 2]       = d0;
            tb32[(g + 8) * 3 + 2] = d2;
        }
    }
    __syncwarp();

    // ---- coalesced writeout: 1536 floats = 384 float4, lane-strided --------
    // Tile j's first 48 smem words are output-ordered -> out words [j*48, j*48+48).
    float* __restrict__ orow = out + ((long long)row * T_LEN + wbase) * 3;
    float4* __restrict__ o4 = reinterpret_cast<float4*>(orow);
    #pragma unroll
    for (int q = lane; q < 384; q += 32) {
        int j = q / 12;
        int w = q - j * 12;
        o4[q] = *reinterpret_cast<const float4*>(featb + j * TPITCH + w * 16);
    }
}

extern "C" void kernel_launch(void* const* d_in, const int* in_sizes, int n_in,
                              void* d_out, int out_size)
{
    const float* s  = (const float*)d_in[0];   // [B*T]
    const float* W1 = (const float*)d_in[1];   // [6*32]
    const float* b1 = (const float*)d_in[2];   // [32]
    const float* W2 = (const float*)d_in[3];   // [32*3]
    const float* b2 = (const float*)d_in[4];   // [3]
    float* out = (float*)d_out;                // [B*T*3]

    int B = in_sizes[0] / T_LEN;
    dim3 grid(T_LEN / WTILE, B);
    gate_router_mma<<<grid, 32>>>(s, W1, b1, W2, b2, out);
}

// round 12
// speedup vs baseline: 1.9994x; 1.0119x over previous
#include <cuda_runtime.h>
#include <cuda_fp16.h>

// Problem constants (fixed by setup_inputs)
#define T_LEN    131072
#define K_WIN    31
#define HALO     15
#define WTILE    512          // elements per 1-warp block; T_LEN/WTILE = 256
#define CHUNK    16           // consecutive elements per thread (= one MMA tile)
#define TPITCH   272          // bytes per 16-element tile in feat buffer (17*16)
#define EPS      1e-6f
#define KURT_MAX 20.0f

typedef unsigned long long ull;

// ---- packed f32x2 helpers ---------------------------------------------------
__device__ __forceinline__ ull pack2(float lo, float hi) {
    ull r; asm("mov.b64 %0, {%1, %2};" : "=l"(r) : "f"(lo), "f"(hi)); return r;
}
__device__ __forceinline__ void unpack2(ull a, float &lo, float &hi) {
    asm("mov.b64 {%0, %1}, %2;" : "=f"(lo), "=f"(hi) : "l"(a));
}
__device__ __forceinline__ ull mul2(ull a, ull b) {
    ull d; asm("mul.rn.f32x2 %0, %1, %2;" : "=l"(d) : "l"(a), "l"(b)); return d;
}
__device__ __forceinline__ ull add2(ull a, ull b) {
    ull d; asm("add.rn.f32x2 %0, %1, %2;" : "=l"(d) : "l"(a), "l"(b)); return d;
}
__device__ __forceinline__ ull fma2(ull a, ull b, ull c) {
    ull d; asm("fma.rn.f32x2 %0, %1, %2, %3;" : "=l"(d) : "l"(a), "l"(b), "l"(c));
    return d;
}

// ---- f16 helpers ------------------------------------------------------------
// pack two f32 into f16x2: low half = lo, high half = hi (cvt d,a,b -> hi=a, lo=b)
__device__ __forceinline__ unsigned h2_of(float lo, float hi) {
    unsigned r; asm("cvt.rn.f16x2.f32 %0, %1, %2;" : "=r"(r) : "f"(hi), "f"(lo)); return r;
}
__device__ __forceinline__ unsigned hmax2_zero(unsigned a) {
    unsigned r; asm("max.f16x2 %0, %1, %2;" : "=r"(r) : "r"(a), "r"(0u)); return r;
}

// mma.m16n8k8 row.col f32.f16.f16.f32 : D += A*B
__device__ __forceinline__ void mma_f16k8(float& c0, float& c1, float& c2, float& c3,
                                          unsigned a0, unsigned a1, unsigned b0) {
    asm volatile("mma.sync.aligned.m16n8k8.row.col.f32.f16.f16.f32 "
                 "{%0,%1,%2,%3}, {%4,%5}, {%6}, {%0,%1,%2,%3};"
                 : "+f"(c0), "+f"(c1), "+f"(c2), "+f"(c3)
                 : "r"(a0), "r"(a1), "r"(b0));
}
// mma.m16n8k16 row.col f32.f16.f16.f32 : D += A*B
__device__ __forceinline__ void mma_f16(float& c0, float& c1, float& c2, float& c3,
                                        unsigned a0, unsigned a1, unsigned a2, unsigned a3,
                                        unsigned b0, unsigned b1) {
    asm volatile("mma.sync.aligned.m16n8k16.row.col.f32.f16.f16.f32 "
                 "{%0,%1,%2,%3}, {%4,%5,%6,%7}, {%8,%9}, {%0,%1,%2,%3};"
                 : "+f"(c0), "+f"(c1), "+f"(c2), "+f"(c3)
                 : "r"(a0), "r"(a1), "r"(a2), "r"(a3), "r"(b0), "r"(b1));
}

// One warp per block. Warp handles WTILE=512 contiguous elements of one row.
__global__ __launch_bounds__(32, 20)
void gate_router_mma(const float* __restrict__ s,
                     const float* __restrict__ W1, const float* __restrict__ b1,
                     const float* __restrict__ W2, const float* __restrict__ b2,
                     float* __restrict__ out)
{
    __shared__ float xs[WTILE + 2 * HALO + 2];                 // 544 floats
    // Feature staging: 32 tiles x TPITCH bytes; tile j = 16 elems x 16B f16
    // records. After tile j's A-fragments are consumed, its region is reused
    // as f32 logit staging (48 words, output-ordered).
    __shared__ __align__(16) unsigned char featb[32 * TPITCH]; // 8704 B

    const int lane = threadIdx.x;
    const int g  = lane >> 2;       // 0..7  (fragment group = row)
    const int tq = lane & 3;        // 0..3  (thread-in-group)
    const int wbase = blockIdx.x * WTILE;
    const int row = blockIdx.y;
    const float* __restrict__ srow = s + (long long)row * T_LEN;

    // ---- stage signal + halo (clamp == replicate padding) ------------------
    for (int i = lane; i < WTILE + 2 * HALO + 2; i += 32) {
        int gg = wbase - HALO + i;
        gg = max(0, min(T_LEN - 1, gg));
        xs[i] = srow[gg];
    }

    // ---- constant fragments (registers) ------------------------------------
    // GEMM1 B (f16, m16n8k8): b = {W1eff[2tq][n], W1eff[2tq+1][n]}, n = ni*8+g.
    // W1eff rows: 0..5 = W1, 6 = b1 (bias folded; feature 6 == 1.0), 7 = 0.
    unsigned B1[4];
    #pragma unroll
    for (int ni = 0; ni < 4; ++ni) {
        int n = ni * 8 + g;
        int k0 = 2 * tq, k1 = 2 * tq + 1;
        float wlo = (k0 < 6) ? W1[k0 * 32 + n] : b1[n];   // k0 in {0,2,4,6}
        float whi = (k1 < 6) ? W1[k1 * 32 + n] : 0.0f;    // k1 in {1,3,5,7}
        B1[ni] = h2_of(wlo, whi);
    }
    // GEMM2 B (f16, m16n8k16): per kp, b0 = {W2eff[16kp+2tq][g], [+1][g]}, b1 = +8,+9.
    unsigned B2[2][2];
    #pragma unroll
    for (int kp = 0; kp < 2; ++kp) {
        int j0 = kp * 16 + 2 * tq;
        float w00 = (g < 3) ? W2[(j0    ) * 3 + g] : 0.0f;
        float w01 = (g < 3) ? W2[(j0 + 1) * 3 + g] : 0.0f;
        float w10 = (g < 3) ? W2[(j0 + 8) * 3 + g] : 0.0f;
        float w11 = (g < 3) ? W2[(j0 + 9) * 3 + g] : 0.0f;
        B2[kp][0] = h2_of(w00, w01);
        B2[kp][1] = h2_of(w10, w11);
    }
    float cI0 = (2 * tq     < 3) ? b2[2 * tq]     : 0.0f;
    float cI1 = (2 * tq + 1 < 3) ? b2[2 * tq + 1] : 0.0f;

    __syncthreads();   // xs visible

    // ---- features: dual sliding chains (elements e and e+8), f32x2-packed --
    const int base = lane * CHUNK;            // xs index of (t0 - 15)
    const int t0 = wbase + base;
    unsigned char* myTile = featb + lane * TPITCH;   // thread's elements = tile `lane`

    const ull INV31p = pack2(1.0f / 31.0f, 1.0f / 31.0f);
    const ull CM1    = pack2(-1.0f, -1.0f);
    const ull CM4    = pack2(-4.0f, -4.0f);
    const ull C6     = pack2( 6.0f,  6.0f);
    const ull CM3    = pack2(-3.0f, -3.0f);
    const ull CEPS   = pack2(EPS, EPS);
    const unsigned ONE_ZERO = 0x00003C00u;    // lo = 1.0h (feature 6), hi = 0

    ull S1 = 0ull, S2 = 0ull, S3 = 0ull, S4 = 0ull;   // (chainA, chainB)
    #pragma unroll
    for (int k = 0; k < K_WIN; ++k) {
        ull v  = pack2(xs[base + k], xs[base + 8 + k]);
        ull v2 = mul2(v, v);
        ull v3 = mul2(v2, v);
        ull v4 = mul2(v2, v2);
        S1 = add2(S1, v);  S2 = add2(S2, v2);
        S3 = add2(S3, v3); S4 = add2(S4, v4);
    }

    #pragma unroll
    for (int p = 0; p < 8; ++p) {
        const int iA = base + p, iB = base + 8 + p;
        // packed moments
        ull mu  = mul2(S1, INV31p);
        ull m2  = mul2(S2, INV31p);
        ull m3  = mul2(S3, INV31p);
        ull m4  = mul2(S4, INV31p);
        ull mu2 = mul2(mu, mu);
        ull var = add2(fma2(mu2, CM1, m2), CEPS);
        ull acc = fma2(mul2(mu, m3), CM4, m4);
        acc = fma2(mul2(mu2, m2), C6, acc);
        acc = fma2(mul2(mu2, mu2), CM3, acc);
        ull vv = mul2(var, var);

        float m4cA, m4cB, vvA, vvB, muA, muB, varA, varB;
        unpack2(acc, m4cA, m4cB);
        unpack2(vv,  vvA,  vvB);
        unpack2(mu,  muA,  muB);
        unpack2(var, varA, varB);
        float kurtA = fminf(__fdividef(m4cA, vvA), KURT_MAX);
        float kurtB = fminf(__fdividef(m4cB, vvB), KURT_MAX);

        // diffs (scalar; clamp staging makes d1 at t=0 vanish naturally)
        float xmA = xs[iA + 14], xA = xs[iA + 15], xpA = xs[iA + 16];
        float xmB = xs[iB + 14], xB = xs[iB + 15], xpB = xs[iB + 16];
        float d1A = fabsf(xA - xmA);
        float d1B = fabsf(xB - xmB);
        float d2A = fabsf(xpA - 2.0f * xA + xmA);
        float d2B = fabsf(xpB - 2.0f * xB + xmB);
        int tA = t0 + p, tB = t0 + 8 + p;
        if (tA == 0 || tA == T_LEN - 1) d2A = 0.0f;
        if (tB == 0 || tB == T_LEN - 1) d2B = 0.0f;

        // f16 records {x,d1,d2,mu,var,kurt,1,0} -> rows p and p+8 of tile `lane`
        uint4 rA;
        rA.x = h2_of(xA, d1A); rA.y = h2_of(d2A, muA);
        rA.z = h2_of(varA, kurtA); rA.w = ONE_ZERO;
        *reinterpret_cast<uint4*>(myTile + p * 16) = rA;
        uint4 rB;
        rB.x = h2_of(xB, d1B); rB.y = h2_of(d2B, muB);
        rB.z = h2_of(varB, kurtB); rB.w = ONE_ZERO;
        *reinterpret_cast<uint4*>(myTile + (p + 8) * 16) = rB;

        // packed slide: add xs[i+31], drop xs[i]   (max read: base+46 < 544)
        ull xa  = pack2(xs[iA + 31], xs[iB + 31]);
        ull xr  = pack2(xs[iA], xs[iB]);
        ull xa2 = mul2(xa, xa), xr2 = mul2(xr, xr);
        S1 = fma2(xr,  CM1, add2(S1, xa));
        S2 = fma2(xr2, CM1, add2(S2, xa2));
        ull xa3 = mul2(xa2, xa), xr3 = mul2(xr2, xr);
        S3 = fma2(xr3, CM1, add2(S3, xa3));
        ull xa4 = mul2(xa2, xa2), xr4 = mul2(xr2, xr2);
        S4 = fma2(xr4, CM1, add2(S4, xa4));
    }
    __syncwarp();

    // ---- 32 tiles: GEMM1 (f16 k8) -> relu/pack -> GEMM2 (f16 k16) ----------
    #pragma unroll 4
    for (int j = 0; j < 32; ++j) {
        const unsigned char* tb = featb + j * TPITCH + g * 16 + tq * 4;
        unsigned a0 = *reinterpret_cast<const unsigned*>(tb);         // row j*16+g
        unsigned a1 = *reinterpret_cast<const unsigned*>(tb + 128);   // row j*16+g+8

        float c0[4], c1[4], c2[4], c3[4];     // hidden cols 8ni+2tq,+1; rows g, g+8
        #pragma unroll
        for (int ni = 0; ni < 4; ++ni) {
            c0[ni] = 0.f; c1[ni] = 0.f; c2[ni] = 0.f; c3[ni] = 0.f;
            mma_f16k8(c0[ni], c1[ni], c2[ni], c3[ni], a0, a1, B1[ni]);
        }

        // relu + pack: C frags == f16 A-frag layout of m16n8k16 (register chain)
        unsigned A2[2][4];
        #pragma unroll
        for (int ni = 0; ni < 4; ++ni) {
            unsigned p0 = hmax2_zero(h2_of(c0[ni], c1[ni]));   // row g
            unsigned p1 = hmax2_zero(h2_of(c2[ni], c3[ni]));   // row g+8
            A2[ni >> 1][(ni & 1) ? 2 : 0] = p0;
            A2[ni >> 1][(ni & 1) ? 3 : 1] = p1;
        }

        float d0 = cI0, d1 = cI1, d2 = cI0, d3 = cI1;
        mma_f16(d0, d1, d2, d3, A2[0][0], A2[0][1], A2[0][2], A2[0][3], B2[0][0], B2[0][1]);
        mma_f16(d0, d1, d2, d3, A2[1][0], A2[1][1], A2[1][2], A2[1][3], B2[1][0], B2[1][1]);

        // WAR-safe without syncwarp: A-loads of tile j precede the warp-
        // converging mma.sync; these stores depend on GEMM2 results.
        float* tb32 = reinterpret_cast<float*>(featb + j * TPITCH);
        if (tq == 0) {                        // D cols 0,1
            tb32[g * 3]           = d0;
            tb32[g * 3 + 1]       = d1;
            tb32[(g + 8) * 3]     = d2;
            tb32[(g + 8) * 3 + 1] = d3;
        } else if (tq == 1) {                 // D col 2 (col 3 = pad)
            tb32[g * 3 + 2]       = d0;
            tb32[(g + 8) * 3 + 2] = d2;
        }
    }
    __syncwarp();

    // ---- coalesced writeout: 1536 floats = 384 float4, lane-strided --------
    float* __restrict__ orow = out + ((long long)row * T_LEN + wbase) * 3;
    float4* __restrict__ o4 = reinterpret_cast<float4*>(orow);
    #pragma unroll
    for (int q = lane; q < 384; q += 32) {
        int j = q / 12;
        int w = q - j * 12;
        o4[q] = *reinterpret_cast<const float4*>(featb + j * TPITCH + w * 16);
    }
}

extern "C" void kernel_launch(void* const* d_in, const int* in_sizes, int n_in,
                              void* d_out, int out_size)
{
    const float* s  = (const float*)d_in[0];   // [B*T]
    const float* W1 = (const float*)d_in[1];   // [6*32]
    const float* b1 = (const float*)d_in[2];   // [32]
    const float* W2 = (const float*)d_in[3];   // [32*3]
    const float* b2 = (const float*)d_in[4];   // [3]
    float* out = (float*)d_out;                // [B*T*3]

    int B = in_sizes[0] / T_LEN;
    dim3 grid(T_LEN / WTILE, B);
    gate_router_mma<<<grid, 32>>>(s, W1, b1, W2, b2, out);
}

// round 13
// speedup vs baseline: 2.2338x; 1.1172x over previous
#include <cuda_runtime.h>
#include <cuda_fp16.h>

// Problem constants (fixed by setup_inputs)
#define T_LEN    131072
#define K_WIN    31
#define HALO     15
#define WTILE    512          // elements per 1-warp block; T_LEN/WTILE = 256
#define CHUNK    16           // consecutive elements per thread (= one MMA tile)
#define TPITCH   272          // bytes per 16-element tile in feat buffer (17*16)
#define EPS      1e-6f
#define KURT_MAX 20.0f

typedef unsigned long long ull;

// ---- packed f32x2 helpers ---------------------------------------------------
__device__ __forceinline__ ull pack2(float lo, float hi) {
    ull r; asm("mov.b64 %0, {%1, %2};" : "=l"(r) : "f"(lo), "f"(hi)); return r;
}
__device__ __forceinline__ void unpack2(ull a, float &lo, float &hi) {
    asm("mov.b64 {%0, %1}, %2;" : "=f"(lo), "=f"(hi) : "l"(a));
}
__device__ __forceinline__ ull mul2(ull a, ull b) {
    ull d; asm("mul.rn.f32x2 %0, %1, %2;" : "=l"(d) : "l"(a), "l"(b)); return d;
}
__device__ __forceinline__ ull add2(ull a, ull b) {
    ull d; asm("add.rn.f32x2 %0, %1, %2;" : "=l"(d) : "l"(a), "l"(b)); return d;
}
__device__ __forceinline__ ull fma2(ull a, ull b, ull c) {
    ull d; asm("fma.rn.f32x2 %0, %1, %2, %3;" : "=l"(d) : "l"(a), "l"(b), "l"(c));
    return d;
}

// ---- f16 helpers ------------------------------------------------------------
// pack two f32 into f16x2: low half = lo, high half = hi (cvt d,a,b -> hi=a, lo=b)
__device__ __forceinline__ unsigned h2_of(float lo, float hi) {
    unsigned r; asm("cvt.rn.f16x2.f32 %0, %1, %2;" : "=r"(r) : "f"(hi), "f"(lo)); return r;
}
__device__ __forceinline__ unsigned hmax2_zero(unsigned a) {
    unsigned r; asm("max.f16x2 %0, %1, %2;" : "=r"(r) : "r"(a), "r"(0u)); return r;
}

// mma.m16n8k8 row.col f32.f16.f16.f32 : D += A*B
__device__ __forceinline__ void mma_f16k8(float& c0, float& c1, float& c2, float& c3,
                                          unsigned a0, unsigned a1, unsigned b0) {
    asm volatile("mma.sync.aligned.m16n8k8.row.col.f32.f16.f16.f32 "
                 "{%0,%1,%2,%3}, {%4,%5}, {%6}, {%0,%1,%2,%3};"
                 : "+f"(c0), "+f"(c1), "+f"(c2), "+f"(c3)
                 : "r"(a0), "r"(a1), "r"(b0));
}
// mma.m16n8k16 row.col f32.f16.f16.f32 : D += A*B
__device__ __forceinline__ void mma_f16(float& c0, float& c1, float& c2, float& c3,
                                        unsigned a0, unsigned a1, unsigned a2, unsigned a3,
                                        unsigned b0, unsigned b1) {
    asm volatile("mma.sync.aligned.m16n8k16.row.col.f32.f16.f16.f32 "
                 "{%0,%1,%2,%3}, {%4,%5,%6,%7}, {%8,%9}, {%0,%1,%2,%3};"
                 : "+f"(c0), "+f"(c1), "+f"(c2), "+f"(c3)
                 : "r"(a0), "r"(a1), "r"(a2), "r"(a3), "r"(b0), "r"(b1));
}

// One warp per block. Warp handles WTILE=512 contiguous elements of one row.
__global__ __launch_bounds__(32, 18)
void gate_router_mma(const float* __restrict__ s,
                     const float* __restrict__ W1, const float* __restrict__ b1,
                     const float* __restrict__ W2, const float* __restrict__ b2,
                     float* __restrict__ out)
{
    __shared__ float xs[WTILE + 2 * HALO + 2];                 // 544 floats
    // Feature staging: 32 tiles x TPITCH bytes; tile j = 16 elems x 16B f16
    // records. After tile j's A-fragments are consumed, its region is reused
    // as f32 logit staging (48 words, output-ordered).
    __shared__ __align__(16) unsigned char featb[32 * TPITCH]; // 8704 B

    const int lane = threadIdx.x;
    const int g  = lane >> 2;       // 0..7  (fragment group = row)
    const int tq = lane & 3;        // 0..3  (thread-in-group)
    const int wbase = blockIdx.x * WTILE;
    const int row = blockIdx.y;
    const float* __restrict__ srow = s + (long long)row * T_LEN;

    // ---- stage signal + halo (clamp == replicate padding) ------------------
    for (int i = lane; i < WTILE + 2 * HALO + 2; i += 32) {
        int gg = wbase - HALO + i;
        gg = max(0, min(T_LEN - 1, gg));
        xs[i] = srow[gg];
    }

    // ---- constant fragments (registers) ------------------------------------
    // GEMM1 B (f16, m16n8k8): b = {W1eff[2tq][n], W1eff[2tq+1][n]}, n = ni*8+g.
    // W1eff rows: 0..5 = W1, 6 = b1 (bias folded; feature 6 == 1.0), 7 = 0.
    unsigned B1[4];
    #pragma unroll
    for (int ni = 0; ni < 4; ++ni) {
        int n = ni * 8 + g;
        int k0 = 2 * tq, k1 = 2 * tq + 1;
        float wlo = (k0 < 6) ? W1[k0 * 32 + n] : b1[n];   // k0 in {0,2,4,6}
        float whi = (k1 < 6) ? W1[k1 * 32 + n] : 0.0f;    // k1 in {1,3,5,7}
        B1[ni] = h2_of(wlo, whi);
    }
    // GEMM2 B (f16, m16n8k16): per kp, b0 = {W2eff[16kp+2tq][g], [+1][g]}, b1 = +8,+9.
    unsigned B2[2][2];
    #pragma unroll
    for (int kp = 0; kp < 2; ++kp) {
        int j0 = kp * 16 + 2 * tq;
        float w00 = (g < 3) ? W2[(j0    ) * 3 + g] : 0.0f;
        float w01 = (g < 3) ? W2[(j0 + 1) * 3 + g] : 0.0f;
        float w10 = (g < 3) ? W2[(j0 + 8) * 3 + g] : 0.0f;
        float w11 = (g < 3) ? W2[(j0 + 9) * 3 + g] : 0.0f;
        B2[kp][0] = h2_of(w00, w01);
        B2[kp][1] = h2_of(w10, w11);
    }
    float cI0 = (2 * tq     < 3) ? b2[2 * tq]     : 0.0f;
    float cI1 = (2 * tq + 1 < 3) ? b2[2 * tq + 1] : 0.0f;

    __syncthreads();   // xs visible

    // ---- features: dual sliding chains (elements e and e+8), f32x2-packed --
    const int base = lane * CHUNK;            // xs index of (t0 - 15)
    const int t0 = wbase + base;
    unsigned char* myTile = featb + lane * TPITCH;   // thread's elements = tile `lane`

    const ull INV31p = pack2(1.0f / 31.0f, 1.0f / 31.0f);
    const ull CM1    = pack2(-1.0f, -1.0f);
    const ull CM4    = pack2(-4.0f, -4.0f);
    const ull C6     = pack2( 6.0f,  6.0f);
    const ull CM3    = pack2(-3.0f, -3.0f);
    const ull CEPS   = pack2(EPS, EPS);
    const unsigned ONE_ZERO = 0x00003C00u;    // lo = 1.0h (feature 6), hi = 0

    ull S1 = 0ull, S2 = 0ull, S3 = 0ull, S4 = 0ull;   // (chainA, chainB)
    #pragma unroll
    for (int k = 0; k < K_WIN; ++k) {
        ull v  = pack2(xs[base + k], xs[base + 8 + k]);
        ull v2 = mul2(v, v);
        ull v3 = mul2(v2, v);
        ull v4 = mul2(v2, v2);
        S1 = add2(S1, v);  S2 = add2(S2, v2);
        S3 = add2(S3, v3); S4 = add2(S4, v4);
    }

    #pragma unroll
    for (int p = 0; p < 8; ++p) {
        const int iA = base + p, iB = base + 8 + p;
        // packed moments
        ull mu  = mul2(S1, INV31p);
        ull m2  = mul2(S2, INV31p);
        ull m3  = mul2(S3, INV31p);
        ull m4  = mul2(S4, INV31p);
        ull mu2 = mul2(mu, mu);
        ull var = add2(fma2(mu2, CM1, m2), CEPS);
        ull acc = fma2(mul2(mu, m3), CM4, m4);
        acc = fma2(mul2(mu2, m2), C6, acc);
        acc = fma2(mul2(mu2, mu2), CM3, acc);
        ull vv = mul2(var, var);

        float m4cA, m4cB, vvA, vvB, muA, muB, varA, varB;
        unpack2(acc, m4cA, m4cB);
        unpack2(vv,  vvA,  vvB);
        unpack2(mu,  muA,  muB);
        unpack2(var, varA, varB);
        float kurtA = fminf(__fdividef(m4cA, vvA), KURT_MAX);
        float kurtB = fminf(__fdividef(m4cB, vvB), KURT_MAX);

        // diffs (scalar; clamp staging makes d1 at t=0 vanish naturally)
        float xmA = xs[iA + 14], xA = xs[iA + 15], xpA = xs[iA + 16];
        float xmB = xs[iB + 14], xB = xs[iB + 15], xpB = xs[iB + 16];
        float d1A = fabsf(xA - xmA);
        float d1B = fabsf(xB - xmB);
        float d2A = fabsf(xpA - 2.0f * xA + xmA);
        float d2B = fabsf(xpB - 2.0f * xB + xmB);
        int tA = t0 + p, tB = t0 + 8 + p;
        if (tA == 0 || tA == T_LEN - 1) d2A = 0.0f;
        if (tB == 0 || tB == T_LEN - 1) d2B = 0.0f;

        // f16 records {x,d1,d2,mu,var,kurt,1,0} -> rows p and p+8 of tile `lane`
        uint4 rA;
        rA.x = h2_of(xA, d1A); rA.y = h2_of(d2A, muA);
        rA.z = h2_of(varA, kurtA); rA.w = ONE_ZERO;
        *reinterpret_cast<uint4*>(myTile + p * 16) = rA;
        uint4 rB;
        rB.x = h2_of(xB, d1B); rB.y = h2_of(d2B, muB);
        rB.z = h2_of(varB, kurtB); rB.w = ONE_ZERO;
        *reinterpret_cast<uint4*>(myTile + (p + 8) * 16) = rB;

        // packed slide: add xs[i+31], drop xs[i]   (max read: base+46 < 544)
        ull xa  = pack2(xs[iA + 31], xs[iB + 31]);
        ull xr  = pack2(xs[iA], xs[iB]);
        ull xa2 = mul2(xa, xa), xr2 = mul2(xr, xr);
        S1 = fma2(xr,  CM1, add2(S1, xa));
        S2 = fma2(xr2, CM1, add2(S2, xa2));
        ull xa3 = mul2(xa2, xa), xr3 = mul2(xr2, xr);
        S3 = fma2(xr3, CM1, add2(S3, xa3));
        ull xa4 = mul2(xa2, xa2), xr4 = mul2(xr2, xr2);
        S4 = fma2(xr4, CM1, add2(S4, xa4));
    }
    __syncwarp();

    // ---- 16 pairs of tiles: two independent GEMM1->relu->GEMM2 chains ------
    // interleaved per iteration to double in-warp ILP (hides LDS + MMA latency).
    #pragma unroll 2
    for (int jp = 0; jp < 16; ++jp) {
        const unsigned char* tbA = featb + (2 * jp) * TPITCH + g * 16 + tq * 4;
        const unsigned char* tbB = tbA + TPITCH;
        unsigned aA0 = *reinterpret_cast<const unsigned*>(tbA);
        unsigned aA1 = *reinterpret_cast<const unsigned*>(tbA + 128);
        unsigned aB0 = *reinterpret_cast<const unsigned*>(tbB);
        unsigned aB1 = *reinterpret_cast<const unsigned*>(tbB + 128);

        float cA0[4], cA1[4], cA2[4], cA3[4];
        float cB0[4], cB1[4], cB2[4], cB3[4];
        #pragma unroll
        for (int ni = 0; ni < 4; ++ni) {
            cA0[ni] = 0.f; cA1[ni] = 0.f; cA2[ni] = 0.f; cA3[ni] = 0.f;
            cB0[ni] = 0.f; cB1[ni] = 0.f; cB2[ni] = 0.f; cB3[ni] = 0.f;
            mma_f16k8(cA0[ni], cA1[ni], cA2[ni], cA3[ni], aA0, aA1, B1[ni]);
            mma_f16k8(cB0[ni], cB1[ni], cB2[ni], cB3[ni], aB0, aB1, B1[ni]);
        }

        // relu + pack: C frags == f16 A-frag layout of m16n8k16 (register chain)
        unsigned A2A[2][4], A2B[2][4];
        #pragma unroll
        for (int ni = 0; ni < 4; ++ni) {
            unsigned pA0 = hmax2_zero(h2_of(cA0[ni], cA1[ni]));   // row g
            unsigned pA1 = hmax2_zero(h2_of(cA2[ni], cA3[ni]));   // row g+8
            unsigned pB0 = hmax2_zero(h2_of(cB0[ni], cB1[ni]));
            unsigned pB1 = hmax2_zero(h2_of(cB2[ni], cB3[ni]));
            A2A[ni >> 1][(ni & 1) ? 2 : 0] = pA0;
            A2A[ni >> 1][(ni & 1) ? 3 : 1] = pA1;
            A2B[ni >> 1][(ni & 1) ? 2 : 0] = pB0;
            A2B[ni >> 1][(ni & 1) ? 3 : 1] = pB1;
        }

        float dA0 = cI0, dA1 = cI1, dA2 = cI0, dA3 = cI1;
        float dB0 = cI0, dB1 = cI1, dB2 = cI0, dB3 = cI1;
        mma_f16(dA0, dA1, dA2, dA3, A2A[0][0], A2A[0][1], A2A[0][2], A2A[0][3], B2[0][0], B2[0][1]);
        mma_f16(dB0, dB1, dB2, dB3, A2B[0][0], A2B[0][1], A2B[0][2], A2B[0][3], B2[0][0], B2[0][1]);
        mma_f16(dA0, dA1, dA2, dA3, A2A[1][0], A2A[1][1], A2A[1][2], A2A[1][3], B2[1][0], B2[1][1]);
        mma_f16(dB0, dB1, dB2, dB3, A2B[1][0], A2B[1][1], A2B[1][2], A2B[1][3], B2[1][0], B2[1][1]);

        // WAR-safe without syncwarp: A-loads of both tiles precede the warp-
        // converging mma.sync; these stores depend on GEMM2 results.
        float* tA32 = reinterpret_cast<float*>(featb + (2 * jp) * TPITCH);
        float* tB32 = reinterpret_cast<float*>(featb + (2 * jp + 1) * TPITCH);
        if (tq == 0) {                        // D cols 0,1
            tA32[g * 3]           = dA0;
            tA32[g * 3 + 1]       = dA1;
            tA32[(g + 8) * 3]     = dA2;
            tA32[(g + 8) * 3 + 1] = dA3;
            tB32[g * 3]           = dB0;
            tB32[g * 3 + 1]       = dB1;
            tB32[(g + 8) * 3]     = dB2;
            tB32[(g + 8) * 3 + 1] = dB3;
        } else if (tq == 1) {                 // D col 2 (col 3 = pad)
            tA32[g * 3 + 2]       = dA0;
            tA32[(g + 8) * 3 + 2] = dA2;
            tB32[g * 3 + 2]       = dB0;
            tB32[(g + 8) * 3 + 2] = dB2;
        }
    }
    __syncwarp();

    // ---- coalesced writeout: 1536 floats = 384 float4, lane-strided --------
    float* __restrict__ orow = out + ((long long)row * T_LEN + wbase) * 3;
    float4* __restrict__ o4 = reinterpret_cast<float4*>(orow);
    #pragma unroll
    for (int q = lane; q < 384; q += 32) {
        int j = q / 12;
        int w = q - j * 12;
        o4[q] = *reinterpret_cast<const float4*>(featb + j * TPITCH + w * 16);
    }
}

extern "C" void kernel_launch(void* const* d_in, const int* in_sizes, int n_in,
                              void* d_out, int out_size)
{
    const float* s  = (const float*)d_in[0];   // [B*T]
    const float* W1 = (const float*)d_in[1];   // [6*32]
    const float* b1 = (const float*)d_in[2];   // [32]
    const float* W2 = (const float*)d_in[3];   // [32*3]
    const float* b2 = (const float*)d_in[4];   // [3]
    float* out = (float*)d_out;                // [B*T*3]

    int B = in_sizes[0] / T_LEN;
    dim3 grid(T_LEN / WTILE, B);
    gate_router_mma<<<grid, 32>>>(s, W1, b1, W2, b2, out);
}

// round 14
// speedup vs baseline: 2.3799x; 1.0654x over previous
#include <cuda_runtime.h>
#include <cuda_fp16.h>

// Problem constants (fixed by setup_inputs)
#define T_LEN    131072
#define K_WIN    31
#define HALO     15
#define WTILE    512          // elements per 1-warp block; T_LEN/WTILE = 256
#define CHUNK    16           // consecutive elements per thread (= one MMA tile)
#define TPITCH   272          // bytes per 16-element tile in feat buffer (17*16)
#define XSLOG    544          // logical xs length (WTILE + 2*HALO + 2)
#define XSPHYS   580          // skewed physical length (544 + 544/16 + slack)
#define EPS      1e-6f
#define KURT_MAX 20.0f

typedef unsigned long long ull;

// skew: insert one pad word every 16 -> lane stride 17 words, gcd(17,32)=1,
// every lockstep scalar LDS across the warp is bank-conflict-free.
__device__ __forceinline__ int sk(int i) { return i + (i >> 4); }

// ---- packed f32x2 helpers ---------------------------------------------------
__device__ __forceinline__ ull pack2(float lo, float hi) {
    ull r; asm("mov.b64 %0, {%1, %2};" : "=l"(r) : "f"(lo), "f"(hi)); return r;
}
__device__ __forceinline__ void unpack2(ull a, float &lo, float &hi) {
    asm("mov.b64 {%0, %1}, %2;" : "=f"(lo), "=f"(hi) : "l"(a));
}
__device__ __forceinline__ ull mul2(ull a, ull b) {
    ull d; asm("mul.rn.f32x2 %0, %1, %2;" : "=l"(d) : "l"(a), "l"(b)); return d;
}
__device__ __forceinline__ ull add2(ull a, ull b) {
    ull d; asm("add.rn.f32x2 %0, %1, %2;" : "=l"(d) : "l"(a), "l"(b)); return d;
}
__device__ __forceinline__ ull fma2(ull a, ull b, ull c) {
    ull d; asm("fma.rn.f32x2 %0, %1, %2, %3;" : "=l"(d) : "l"(a), "l"(b), "l"(c));
    return d;
}

// ---- f16 helpers ------------------------------------------------------------
// pack two f32 into f16x2: low half = lo, high half = hi (cvt d,a,b -> hi=a, lo=b)
__device__ __forceinline__ unsigned h2_of(float lo, float hi) {
    unsigned r; asm("cvt.rn.f16x2.f32 %0, %1, %2;" : "=r"(r) : "f"(hi), "f"(lo)); return r;
}
__device__ __forceinline__ unsigned hmax2_zero(unsigned a) {
    unsigned r; asm("max.f16x2 %0, %1, %2;" : "=r"(r) : "r"(a), "r"(0u)); return r;
}

// mma.m16n8k8 row.col f32.f16.f16.f32 : D += A*B
__device__ __forceinline__ void mma_f16k8(float& c0, float& c1, float& c2, float& c3,
                                          unsigned a0, unsigned a1, unsigned b0) {
    asm volatile("mma.sync.aligned.m16n8k8.row.col.f32.f16.f16.f32 "
                 "{%0,%1,%2,%3}, {%4,%5}, {%6}, {%0,%1,%2,%3};"
                 : "+f"(c0), "+f"(c1), "+f"(c2), "+f"(c3)
                 : "r"(a0), "r"(a1), "r"(b0));
}
// mma.m16n8k16 row.col f32.f16.f16.f32 : D += A*B
__device__ __forceinline__ void mma_f16(float& c0, float& c1, float& c2, float& c3,
                                        unsigned a0, unsigned a1, unsigned a2, unsigned a3,
                                        unsigned b0, unsigned b1) {
    asm volatile("mma.sync.aligned.m16n8k16.row.col.f32.f16.f16.f32 "
                 "{%0,%1,%2,%3}, {%4,%5,%6,%7}, {%8,%9}, {%0,%1,%2,%3};"
                 : "+f"(c0), "+f"(c1), "+f"(c2), "+f"(c3)
                 : "r"(a0), "r"(a1), "r"(a2), "r"(a3), "r"(b0), "r"(b1));
}

// One warp per block. Warp handles WTILE=512 contiguous elements of one row.
__global__ __launch_bounds__(32, 18)
void gate_router_mma(const float* __restrict__ s,
                     const float* __restrict__ W1, const float* __restrict__ b1,
                     const float* __restrict__ W2, const float* __restrict__ b2,
                     float* __restrict__ out)
{
    __shared__ float xs[XSPHYS];                               // skewed signal
    // Feature staging: 32 tiles x TPITCH bytes; tile j = 16 elems x 16B f16
    // records. After tile j's A-fragments are consumed, its region is reused
    // as f32 logit staging (48 words, output-ordered).
    __shared__ __align__(16) unsigned char featb[32 * TPITCH]; // 8704 B

    const int lane = threadIdx.x;
    const int g  = lane >> 2;       // 0..7  (fragment group = row)
    const int tq = lane & 3;        // 0..3  (thread-in-group)
    const int wbase = blockIdx.x * WTILE;
    const int row = blockIdx.y;
    const float* __restrict__ srow = s + (long long)row * T_LEN;

    // ---- stage signal + halo, skew-addressed (clamp == replicate padding) --
    for (int i = lane; i < XSLOG; i += 32) {
        int gg = wbase - HALO + i;
        gg = max(0, min(T_LEN - 1, gg));
        xs[sk(i)] = srow[gg];
    }

    // ---- constant fragments (registers) ------------------------------------
    // GEMM1 B (f16, m16n8k8): b = {W1eff[2tq][n], W1eff[2tq+1][n]}, n = ni*8+g.
    // W1eff rows: 0..5 = W1, 6 = b1 (bias folded; feature 6 == 1.0), 7 = 0.
    unsigned B1[4];
    #pragma unroll
    for (int ni = 0; ni < 4; ++ni) {
        int n = ni * 8 + g;
        int k0 = 2 * tq, k1 = 2 * tq + 1;
        float wlo = (k0 < 6) ? W1[k0 * 32 + n] : b1[n];   // k0 in {0,2,4,6}
        float whi = (k1 < 6) ? W1[k1 * 32 + n] : 0.0f;    // k1 in {1,3,5,7}
        B1[ni] = h2_of(wlo, whi);
    }
    // GEMM2 B (f16, m16n8k16): per kp, b0 = {W2eff[16kp+2tq][g], [+1][g]}, b1 = +8,+9.
    unsigned B2[2][2];
    #pragma unroll
    for (int kp = 0; kp < 2; ++kp) {
        int j0 = kp * 16 + 2 * tq;
        float w00 = (g < 3) ? W2[(j0    ) * 3 + g] : 0.0f;
        float w01 = (g < 3) ? W2[(j0 + 1) * 3 + g] : 0.0f;
        float w10 = (g < 3) ? W2[(j0 + 8) * 3 + g] : 0.0f;
        float w11 = (g < 3) ? W2[(j0 + 9) * 3 + g] : 0.0f;
        B2[kp][0] = h2_of(w00, w01);
        B2[kp][1] = h2_of(w10, w11);
    }
    float cI0 = (2 * tq     < 3) ? b2[2 * tq]     : 0.0f;
    float cI1 = (2 * tq + 1 < 3) ? b2[2 * tq + 1] : 0.0f;

    __syncthreads();   // xs visible

    // ---- features: dual sliding chains (elements e and e+8), f32x2-packed --
    const int base = lane * CHUNK;            // logical xs index of (t0 - 15)
    const int t0 = wbase + base;
    unsigned char* myTile = featb + lane * TPITCH;   // thread's elements = tile `lane`

    const ull INV31p = pack2(1.0f / 31.0f, 1.0f / 31.0f);
    const ull CM1    = pack2(-1.0f, -1.0f);
    const ull CM4    = pack2(-4.0f, -4.0f);
    const ull C6     = pack2( 6.0f,  6.0f);
    const ull CM3    = pack2(-3.0f, -3.0f);
    const ull CEPS   = pack2(EPS, EPS);
    const unsigned ONE_ZERO = 0x00003C00u;    // lo = 1.0h (feature 6), hi = 0

    ull S1 = 0ull, S2 = 0ull, S3 = 0ull, S4 = 0ull;   // (chainA, chainB)
    #pragma unroll
    for (int k = 0; k < K_WIN; ++k) {
        ull v  = pack2(xs[sk(base + k)], xs[sk(base + 8 + k)]);
        ull v2 = mul2(v, v);
        ull v3 = mul2(v2, v);
        ull v4 = mul2(v2, v2);
        S1 = add2(S1, v);  S2 = add2(S2, v2);
        S3 = add2(S3, v3); S4 = add2(S4, v4);
    }

    // carried diff windows (values identical to reloading; 1 load/elem/chain)
    float xmA = xs[sk(base + 14)],     xA = xs[sk(base + 15)];
    float xmB = xs[sk(base + 8 + 14)], xB = xs[sk(base + 8 + 15)];

    #pragma unroll
    for (int p = 0; p < 8; ++p) {
        const int iA = base + p, iB = base + 8 + p;
        // packed moments
        ull mu  = mul2(S1, INV31p);
        ull m2  = mul2(S2, INV31p);
        ull m3  = mul2(S3, INV31p);
        ull m4  = mul2(S4, INV31p);
        ull mu2 = mul2(mu, mu);
        ull var = add2(fma2(mu2, CM1, m2), CEPS);
        ull acc = fma2(mul2(mu, m3), CM4, m4);
        acc = fma2(mul2(mu2, m2), C6, acc);
        acc = fma2(mul2(mu2, mu2), CM3, acc);
        ull vv = mul2(var, var);

        float m4cA, m4cB, vvA, vvB, muA, muB, varA, varB;
        unpack2(acc, m4cA, m4cB);
        unpack2(vv,  vvA,  vvB);
        unpack2(mu,  muA,  muB);
        unpack2(var, varA, varB);
        float kurtA = fminf(__fdividef(m4cA, vvA), KURT_MAX);
        float kurtB = fminf(__fdividef(m4cB, vvB), KURT_MAX);

        // diffs from carried window + one fresh load per chain
        float xpA = xs[sk(iA + 16)];
        float xpB = xs[sk(iB + 16)];
        float d1A = fabsf(xA - xmA);
        float d1B = fabsf(xB - xmB);
        float d2A = fabsf(xpA - 2.0f * xA + xmA);
        float d2B = fabsf(xpB - 2.0f * xB + xmB);
        int tA = t0 + p, tB = t0 + 8 + p;
        if (tA == 0 || tA == T_LEN - 1) d2A = 0.0f;
        if (tB == 0 || tB == T_LEN - 1) d2B = 0.0f;

        // f16 records {x,d1,d2,mu,var,kurt,1,0} -> rows p and p+8 of tile `lane`
        uint4 rA;
        rA.x = h2_of(xA, d1A); rA.y = h2_of(d2A, muA);
        rA.z = h2_of(varA, kurtA); rA.w = ONE_ZERO;
        *reinterpret_cast<uint4*>(myTile + p * 16) = rA;
        uint4 rB;
        rB.x = h2_of(xB, d1B); rB.y = h2_of(d2B, muB);
        rB.z = h2_of(varB, kurtB); rB.w = ONE_ZERO;
        *reinterpret_cast<uint4*>(myTile + (p + 8) * 16) = rB;

        // packed slide: add xs[i+31], drop xs[i]
        ull xa  = pack2(xs[sk(iA + 31)], xs[sk(iB + 31)]);
        ull xr  = pack2(xs[sk(iA)], xs[sk(iB)]);
        ull xa2 = mul2(xa, xa), xr2 = mul2(xr, xr);
        S1 = fma2(xr,  CM1, add2(S1, xa));
        S2 = fma2(xr2, CM1, add2(S2, xa2));
        ull xa3 = mul2(xa2, xa), xr3 = mul2(xr2, xr);
        S3 = fma2(xr3, CM1, add2(S3, xa3));
        ull xa4 = mul2(xa2, xa2), xr4 = mul2(xr2, xr2);
        S4 = fma2(xr4, CM1, add2(S4, xa4));

        // advance carried windows
        xmA = xA; xA = xpA;
        xmB = xB; xB = xpB;
    }
    __syncwarp();

    // ---- 16 pairs of tiles: two independent GEMM1->relu->GEMM2 chains ------
    // interleaved per iteration to double in-warp ILP (hides LDS + MMA latency).
    #pragma unroll 2
    for (int jp = 0; jp < 16; ++jp) {
        const unsigned char* tbA = featb + (2 * jp) * TPITCH + g * 16 + tq * 4;
        const unsigned char* tbB = tbA + TPITCH;
        unsigned aA0 = *reinterpret_cast<const unsigned*>(tbA);
        unsigned aA1 = *reinterpret_cast<const unsigned*>(tbA + 128);
        unsigned aB0 = *reinterpret_cast<const unsigned*>(tbB);
        unsigned aB1 = *reinterpret_cast<const unsigned*>(tbB + 128);

        float cA0[4], cA1[4], cA2[4], cA3[4];
        float cB0[4], cB1[4], cB2[4], cB3[4];
        #pragma unroll
        for (int ni = 0; ni < 4; ++ni) {
            cA0[ni] = 0.f; cA1[ni] = 0.f; cA2[ni] = 0.f; cA3[ni] = 0.f;
            cB0[ni] = 0.f; cB1[ni] = 0.f; cB2[ni] = 0.f; cB3[ni] = 0.f;
            mma_f16k8(cA0[ni], cA1[ni], cA2[ni], cA3[ni], aA0, aA1, B1[ni]);
            mma_f16k8(cB0[ni], cB1[ni], cB2[ni], cB3[ni], aB0, aB1, B1[ni]);
        }

        // relu + pack: C frags == f16 A-frag layout of m16n8k16 (register chain)
        unsigned A2A[2][4], A2B[2][4];
        #pragma unroll
        for (int ni = 0; ni < 4; ++ni) {
            unsigned pA0 = hmax2_zero(h2_of(cA0[ni], cA1[ni]));   // row g
            unsigned pA1 = hmax2_zero(h2_of(cA2[ni], cA3[ni]));   // row g+8
            unsigned pB0 = hmax2_zero(h2_of(cB0[ni], cB1[ni]));
            unsigned pB1 = hmax2_zero(h2_of(cB2[ni], cB3[ni]));
            A2A[ni >> 1][(ni & 1) ? 2 : 0] = pA0;
            A2A[ni >> 1][(ni & 1) ? 3 : 1] = pA1;
            A2B[ni >> 1][(ni & 1) ? 2 : 0] = pB0;
            A2B[ni >> 1][(ni & 1) ? 3 : 1] = pB1;
        }

        float dA0 = cI0, dA1 = cI1, dA2 = cI0, dA3 = cI1;
        float dB0 = cI0, dB1 = cI1, dB2 = cI0, dB3 = cI1;
        mma_f16(dA0, dA1, dA2, dA3, A2A[0][0], A2A[0][1], A2A[0][2], A2A[0][3], B2[0][0], B2[0][1]);
        mma_f16(dB0, dB1, dB2, dB3, A2B[0][0], A2B[0][1], A2B[0][2], A2B[0][3], B2[0][0], B2[0][1]);
        mma_f16(dA0, dA1, dA2, dA3, A2A[1][0], A2A[1][1], A2A[1][2], A2A[1][3], B2[1][0], B2[1][1]);
        mma_f16(dB0, dB1, dB2, dB3, A2B[1][0], A2B[1][1], A2B[1][2], A2B[1][3], B2[1][0], B2[1][1]);

        // WAR-safe without syncwarp: A-loads of both tiles precede the warp-
        // converging mma.sync; these stores depend on GEMM2 results.
        float* tA32 = reinterpret_cast<float*>(featb + (2 * jp) * TPITCH);
        float* tB32 = reinterpret_cast<float*>(featb + (2 * jp + 1) * TPITCH);
        if (tq == 0) {                        // D cols 0,1
            tA32[g * 3]           = dA0;
            tA32[g * 3 + 1]       = dA1;
            tA32[(g + 8) * 3]     = dA2;
            tA32[(g + 8) * 3 + 1] = dA3;
            tB32[g * 3]           = dB0;
            tB32[g * 3 + 1]       = dB1;
            tB32[(g + 8) * 3]     = dB2;
            tB32[(g + 8) * 3 + 1] = dB3;
        } else if (tq == 1) {                 // D col 2 (col 3 = pad)
            tA32[g * 3 + 2]       = dA0;
            tA32[(g + 8) * 3 + 2] = dA2;
            tB32[g * 3 + 2]       = dB0;
            tB32[(g + 8) * 3 + 2] = dB2;
        }
    }
    __syncwarp();

    // ---- coalesced writeout: 1536 floats = 384 float4, lane-strided --------
    float* __restrict__ orow = out + ((long long)row * T_LEN + wbase) * 3;
    float4* __restrict__ o4 = reinterpret_cast<float4*>(orow);
    #pragma unroll
    for (int q = lane; q < 384; q += 32) {
        int j = q / 12;
        int w = q - j * 12;
        o4[q] = *reinterpret_cast<const float4*>(featb + j * TPITCH + w * 16);
    }
}

extern "C" void kernel_launch(void* const* d_in, const int* in_sizes, int n_in,
                              void* d_out, int out_size)
{
    const float* s  = (const float*)d_in[0];   // [B*T]
    const float* W1 = (const float*)d_in[1];   // [6*32]
    const float* b1 = (const float*)d_in[2];   // [32]
    const float* W2 = (const float*)d_in[3];   // [32*3]
    const float* b2 = (const float*)d_in[4];   // [3]
    float* out = (float*)d_out;                // [B*T*3]

    int B = in_sizes[0] / T_LEN;
    dim3 grid(T_LEN / WTILE, B);
    gate_router_mma<<<grid, 32>>>(s, W1, b1, W2, b2, out);
}

// round 15
// speedup vs baseline: 2.3817x; 1.0007x over previous
#include <cuda_runtime.h>
#include <cuda_fp16.h>

// Problem constants (fixed by setup_inputs)
#define T_LEN    131072
#define K_WIN    31
#define HALO     15
#define WTILE    512          // elements per WARP; 4 warps/CTA
#define CTAW     4
#define NTHREADS (32 * CTAW)
#define CTATILE  (WTILE * CTAW)        // 2048 elements per CTA
#define CHUNK    16           // consecutive elements per thread (= one MMA tile)
#define TPITCH   272          // bytes per 16-element tile in feat buffer (17*16)
#define XSLOG    (CTATILE + 2 * HALO + 2)   // 2080 logical floats
#define XSPHYS   2210                        // skewed physical length
#define EPS      1e-6f
#define KURT_MAX 20.0f

typedef unsigned long long ull;

// skew: insert one pad word every 16 -> lane stride 17 words, gcd(17,32)=1,
// every lockstep scalar LDS across the warp is bank-conflict-free.
__device__ __forceinline__ int sk(int i) { return i + (i >> 4); }

// ---- packed f32x2 helpers ---------------------------------------------------
__device__ __forceinline__ ull pack2(float lo, float hi) {
    ull r; asm("mov.b64 %0, {%1, %2};" : "=l"(r) : "f"(lo), "f"(hi)); return r;
}
__device__ __forceinline__ void unpack2(ull a, float &lo, float &hi) {
    asm("mov.b64 {%0, %1}, %2;" : "=f"(lo), "=f"(hi) : "l"(a));
}
__device__ __forceinline__ ull mul2(ull a, ull b) {
    ull d; asm("mul.rn.f32x2 %0, %1, %2;" : "=l"(d) : "l"(a), "l"(b)); return d;
}
__device__ __forceinline__ ull add2(ull a, ull b) {
    ull d; asm("add.rn.f32x2 %0, %1, %2;" : "=l"(d) : "l"(a), "l"(b)); return d;
}
__device__ __forceinline__ ull fma2(ull a, ull b, ull c) {
    ull d; asm("fma.rn.f32x2 %0, %1, %2, %3;" : "=l"(d) : "l"(a), "l"(b), "l"(c));
    return d;
}

// ---- f16 helpers ------------------------------------------------------------
// pack two f32 into f16x2: low half = lo, high half = hi (cvt d,a,b -> hi=a, lo=b)
__device__ __forceinline__ unsigned h2_of(float lo, float hi) {
    unsigned r; asm("cvt.rn.f16x2.f32 %0, %1, %2;" : "=r"(r) : "f"(hi), "f"(lo)); return r;
}
__device__ __forceinline__ unsigned hmax2_zero(unsigned a) {
    unsigned r; asm("max.f16x2 %0, %1, %2;" : "=r"(r) : "r"(a), "r"(0u)); return r;
}

// mma.m16n8k8 f32.f16.f16.f32, C = broadcast zero register (no acc MOV-init)
__device__ __forceinline__ void mma_f16k8_z(float& d0, float& d1, float& d2, float& d3,
                                            unsigned a0, unsigned a1, unsigned b0,
                                            float z) {
    asm volatile("mma.sync.aligned.m16n8k8.row.col.f32.f16.f16.f32 "
                 "{%0,%1,%2,%3}, {%4,%5}, {%6}, {%7,%7,%7,%7};"
                 : "=f"(d0), "=f"(d1), "=f"(d2), "=f"(d3)
                 : "r"(a0), "r"(a1), "r"(b0), "f"(z));
}
// mma.m16n8k16 with explicit C inputs (consumes bias init directly)
__device__ __forceinline__ void mma_f16_c(float& d0, float& d1, float& d2, float& d3,
                                          unsigned a0, unsigned a1, unsigned a2, unsigned a3,
                                          unsigned b0, unsigned b1,
                                          float c0, float c1, float c2, float c3) {
    asm volatile("mma.sync.aligned.m16n8k16.row.col.f32.f16.f16.f32 "
                 "{%0,%1,%2,%3}, {%4,%5,%6,%7}, {%8,%9}, {%10,%11,%12,%13};"
                 : "=f"(d0), "=f"(d1), "=f"(d2), "=f"(d3)
                 : "r"(a0), "r"(a1), "r"(a2), "r"(a3), "r"(b0), "r"(b1),
                   "f"(c0), "f"(c1), "f"(c2), "f"(c3));
}
// mma.m16n8k16 accumulate in place
__device__ __forceinline__ void mma_f16(float& c0, float& c1, float& c2, float& c3,
                                        unsigned a0, unsigned a1, unsigned a2, unsigned a3,
                                        unsigned b0, unsigned b1) {
    asm volatile("mma.sync.aligned.m16n8k16.row.col.f32.f16.f16.f32 "
                 "{%0,%1,%2,%3}, {%4,%5,%6,%7}, {%8,%9}, {%0,%1,%2,%3};"
                 : "+f"(c0), "+f"(c1), "+f"(c2), "+f"(c3)
                 : "r"(a0), "r"(a1), "r"(a2), "r"(a3), "r"(b0), "r"(b1));
}

// 4 warps per CTA; each warp handles its own 512 contiguous elements.
__global__ __launch_bounds__(NTHREADS, 5)
void gate_router_mma(const float* __restrict__ s,
                     const float* __restrict__ W1, const float* __restrict__ b1,
                     const float* __restrict__ W2, const float* __restrict__ b2,
                     float* __restrict__ out)
{
    __shared__ float xs[XSPHYS];                               // skewed CTA signal
    // Per-warp feature staging: 32 tiles x TPITCH. Tile j's region is reused
    // as f32 logit staging (48 words, output-ordered) after consumption.
    __shared__ __align__(16) unsigned char featb[CTAW * 32 * TPITCH];

    const int tid  = threadIdx.x;
    const int wid  = tid >> 5;
    const int lane = tid & 31;
    const int g  = lane >> 2;       // 0..7  (fragment group = row)
    const int tq = lane & 3;        // 0..3  (thread-in-group)
    const int ctaStart = blockIdx.x * CTATILE;
    const int row = blockIdx.y;
    const float* __restrict__ srow = s + (long long)row * T_LEN;

    // ---- stage CTA signal + halo, 128-wide coalesced, skew-addressed -------
    for (int i = tid; i < XSLOG; i += NTHREADS) {
        int gg = ctaStart - HALO + i;
        gg = max(0, min(T_LEN - 1, gg));
        xs[sk(i)] = srow[gg];
    }

    // ---- constant fragments (registers; identical derivation per warp) -----
    // GEMM1 B (f16, m16n8k8): b = {W1eff[2tq][n], W1eff[2tq+1][n]}, n = ni*8+g.
    // W1eff rows: 0..5 = W1, 6 = b1 (bias folded; feature 6 == 1.0), 7 = 0.
    unsigned B1[4];
    #pragma unroll
    for (int ni = 0; ni < 4; ++ni) {
        int n = ni * 8 + g;
        int k0 = 2 * tq, k1 = 2 * tq + 1;
        float wlo = (k0 < 6) ? W1[k0 * 32 + n] : b1[n];   // k0 in {0,2,4,6}
        float whi = (k1 < 6) ? W1[k1 * 32 + n] : 0.0f;    // k1 in {1,3,5,7}
        B1[ni] = h2_of(wlo, whi);
    }
    // GEMM2 B (f16, m16n8k16): per kp, b0 = {W2eff[16kp+2tq][g], [+1][g]}, b1 = +8,+9.
    unsigned B2[2][2];
    #pragma unroll
    for (int kp = 0; kp < 2; ++kp) {
        int j0 = kp * 16 + 2 * tq;
        float w00 = (g < 3) ? W2[(j0    ) * 3 + g] : 0.0f;
        float w01 = (g < 3) ? W2[(j0 + 1) * 3 + g] : 0.0f;
        float w10 = (g < 3) ? W2[(j0 + 8) * 3 + g] : 0.0f;
        float w11 = (g < 3) ? W2[(j0 + 9) * 3 + g] : 0.0f;
        B2[kp][0] = h2_of(w00, w01);
        B2[kp][1] = h2_of(w10, w11);
    }
    float cI0 = (2 * tq     < 3) ? b2[2 * tq]     : 0.0f;
    float cI1 = (2 * tq + 1 < 3) ? b2[2 * tq + 1] : 0.0f;
    const float fz = 0.0f;                   // shared zero C-operand

    __syncthreads();   // xs visible to all warps

    // ---- features: dual sliding chains (elements e and e+8), f32x2-packed --
    const int base = wid * WTILE + lane * CHUNK;  // logical xs index of (t0 - 15)
    const int t0 = ctaStart + base;
    unsigned char* warpFeat = featb + wid * 32 * TPITCH;
    unsigned char* myTile = warpFeat + lane * TPITCH;

    const ull INV31p = pack2(1.0f / 31.0f, 1.0f / 31.0f);
    const ull CM1    = pack2(-1.0f, -1.0f);
    const ull CM4    = pack2(-4.0f, -4.0f);
    const ull C6     = pack2( 6.0f,  6.0f);
    const ull CM3    = pack2(-3.0f, -3.0f);
    const ull CEPS   = pack2(EPS, EPS);
    const unsigned ONE_ZERO = 0x00003C00u;    // lo = 1.0h (feature 6), hi = 0

    ull S1 = 0ull, S2 = 0ull, S3 = 0ull, S4 = 0ull;   // (chainA, chainB)
    #pragma unroll
    for (int k = 0; k < K_WIN; ++k) {
        ull v  = pack2(xs[sk(base + k)], xs[sk(base + 8 + k)]);
        ull v2 = mul2(v, v);
        ull v3 = mul2(v2, v);
        ull v4 = mul2(v2, v2);
        S1 = add2(S1, v);  S2 = add2(S2, v2);
        S3 = add2(S3, v3); S4 = add2(S4, v4);
    }

    // carried diff windows (values identical to reloading; 1 load/elem/chain)
    float xmA = xs[sk(base + 14)],     xA = xs[sk(base + 15)];
    float xmB = xs[sk(base + 8 + 14)], xB = xs[sk(base + 8 + 15)];

    #pragma unroll
    for (int p = 0; p < 8; ++p) {
        const int iA = base + p, iB = base + 8 + p;
        // packed moments
        ull mu  = mul2(S1, INV31p);
        ull m2  = mul2(S2, INV31p);
        ull m3  = mul2(S3, INV31p);
        ull m4  = mul2(S4, INV31p);
        ull mu2 = mul2(mu, mu);
        ull var = add2(fma2(mu2, CM1, m2), CEPS);
        ull acc = fma2(mul2(mu, m3), CM4, m4);
        acc = fma2(mul2(mu2, m2), C6, acc);
        acc = fma2(mul2(mu2, mu2), CM3, acc);
        ull vv = mul2(var, var);

        float m4cA, m4cB, vvA, vvB, muA, muB, varA, varB;
        unpack2(acc, m4cA, m4cB);
        unpack2(vv,  vvA,  vvB);
        unpack2(mu,  muA,  muB);
        unpack2(var, varA, varB);
        float kurtA = fminf(__fdividef(m4cA, vvA), KURT_MAX);
        float kurtB = fminf(__fdividef(m4cB, vvB), KURT_MAX);

        // diffs from carried window + one fresh load per chain
        float xpA = xs[sk(iA + 16)];
        float xpB = xs[sk(iB + 16)];
        float d1A = fabsf(xA - xmA);
        float d1B = fabsf(xB - xmB);
        float d2A = fabsf(xpA - 2.0f * xA + xmA);
        float d2B = fabsf(xpB - 2.0f * xB + xmB);
        int tA = t0 + p, tB = t0 + 8 + p;
        if (tA == 0 || tA == T_LEN - 1) d2A = 0.0f;
        if (tB == 0 || tB == T_LEN - 1) d2B = 0.0f;

        // f16 records {x,d1,d2,mu,var,kurt,1,0} -> rows p and p+8 of tile `lane`
        uint4 rA;
        rA.x = h2_of(xA, d1A); rA.y = h2_of(d2A, muA);
        rA.z = h2_of(varA, kurtA); rA.w = ONE_ZERO;
        *reinterpret_cast<uint4*>(myTile + p * 16) = rA;
        uint4 rB;
        rB.x = h2_of(xB, d1B); rB.y = h2_of(d2B, muB);
        rB.z = h2_of(varB, kurtB); rB.w = ONE_ZERO;
        *reinterpret_cast<uint4*>(myTile + (p + 8) * 16) = rB;

        // packed slide: add xs[i+31], drop xs[i]
        ull xa  = pack2(xs[sk(iA + 31)], xs[sk(iB + 31)]);
        ull xr  = pack2(xs[sk(iA)], xs[sk(iB)]);
        ull xa2 = mul2(xa, xa), xr2 = mul2(xr, xr);
        S1 = fma2(xr,  CM1, add2(S1, xa));
        S2 = fma2(xr2, CM1, add2(S2, xa2));
        ull xa3 = mul2(xa2, xa), xr3 = mul2(xr2, xr);
        S3 = fma2(xr3, CM1, add2(S3, xa3));
        ull xa4 = mul2(xa2, xa2), xr4 = mul2(xr2, xr2);
        S4 = fma2(xr4, CM1, add2(S4, xa4));

        // advance carried windows
        xmA = xA; xA = xpA;
        xmB = xB; xB = xpB;
    }
    __syncwarp();   // warp-private featb region: warp-level sync suffices

    // ---- 16 pairs of tiles: two independent GEMM1->relu->GEMM2 chains ------
    #pragma unroll 2
    for (int jp = 0; jp < 16; ++jp) {
        const unsigned char* tbA = warpFeat + (2 * jp) * TPITCH + g * 16 + tq * 4;
        const unsigned char* tbB = tbA + TPITCH;
        unsigned aA0 = *reinterpret_cast<const unsigned*>(tbA);
        unsigned aA1 = *reinterpret_cast<const unsigned*>(tbA + 128);
        unsigned aB0 = *reinterpret_cast<const unsigned*>(tbB);
        unsigned aB1 = *reinterpret_cast<const unsigned*>(tbB + 128);

        float cA0[4], cA1[4], cA2[4], cA3[4];
        float cB0[4], cB1[4], cB2[4], cB3[4];
        #pragma unroll
        for (int ni = 0; ni < 4; ++ni) {
            mma_f16k8_z(cA0[ni], cA1[ni], cA2[ni], cA3[ni], aA0, aA1, B1[ni], fz);
            mma_f16k8_z(cB0[ni], cB1[ni], cB2[ni], cB3[ni], aB0, aB1, B1[ni], fz);
        }

        // relu + pack: C frags == f16 A-frag layout of m16n8k16 (register chain)
        unsigned A2A[2][4], A2B[2][4];
        #pragma unroll
        for (int ni = 0; ni < 4; ++ni) {
            unsigned pA0 = hmax2_zero(h2_of(cA0[ni], cA1[ni]));   // row g
            unsigned pA1 = hmax2_zero(h2_of(cA2[ni], cA3[ni]));   // row g+8
            unsigned pB0 = hmax2_zero(h2_of(cB0[ni], cB1[ni]));
            unsigned pB1 = hmax2_zero(h2_of(cB2[ni], cB3[ni]));
            A2A[ni >> 1][(ni & 1) ? 2 : 0] = pA0;
            A2A[ni >> 1][(ni & 1) ? 3 : 1] = pA1;
            A2B[ni >> 1][(ni & 1) ? 2 : 0] = pB0;
            A2B[ni >> 1][(ni & 1) ? 3 : 1] = pB1;
        }

        float dA0, dA1, dA2, dA3, dB0, dB1, dB2, dB3;
        mma_f16_c(dA0, dA1, dA2, dA3, A2A[0][0], A2A[0][1], A2A[0][2], A2A[0][3],
                  B2[0][0], B2[0][1], cI0, cI1, cI0, cI1);
        mma_f16_c(dB0, dB1, dB2, dB3, A2B[0][0], A2B[0][1], A2B[0][2], A2B[0][3],
                  B2[0][0], B2[0][1], cI0, cI1, cI0, cI1);
        mma_f16(dA0, dA1, dA2, dA3, A2A[1][0], A2A[1][1], A2A[1][2], A2A[1][3], B2[1][0], B2[1][1]);
        mma_f16(dB0, dB1, dB2, dB3, A2B[1][0], A2B[1][1], A2B[1][2], A2B[1][3], B2[1][0], B2[1][1]);

        // WAR-safe without syncwarp: A-loads of both tiles precede the warp-
        // converging mma.sync; these stores depend on GEMM2 results.
        float* tA32 = reinterpret_cast<float*>(warpFeat + (2 * jp) * TPITCH);
        float* tB32 = reinterpret_cast<float*>(warpFeat + (2 * jp + 1) * TPITCH);
        if (tq == 0) {                        // D cols 0,1
            tA32[g * 3]           = dA0;
            tA32[g * 3 + 1]       = dA1;
            tA32[(g + 8) * 3]     = dA2;
            tA32[(g + 8) * 3 + 1] = dA3;
            tB32[g * 3]           = dB0;
            tB32[g * 3 + 1]       = dB1;
            tB32[(g + 8) * 3]     = dB2;
            tB32[(g + 8) * 3 + 1] = dB3;
        } else if (tq == 1) {                 // D col 2 (col 3 = pad)
            tA32[g * 3 + 2]       = dA0;
            tA32[(g + 8) * 3 + 2] = dA2;
            tB32[g * 3 + 2]       = dB0;
            tB32[(g + 8) * 3 + 2] = dB2;
        }
    }
    __syncwarp();

    // ---- coalesced writeout: 1536 floats = 384 float4 per warp -------------
    float* __restrict__ orow = out + ((long long)row * T_LEN + ctaStart + wid * WTILE) * 3;
    float4* __restrict__ o4 = reinterpret_cast<float4*>(orow);
    #pragma unroll
    for (int q = lane; q < 384; q += 32) {
        int j = q / 12;
        int w = q - j * 12;
        o4[q] = *reinterpret_cast<const float4*>(warpFeat + j * TPITCH + w * 16);
    }
}

extern "C" void kernel_launch(void* const* d_in, const int* in_sizes, int n_in,
                              void* d_out, int out_size)
{
    const float* s  = (const float*)d_in[0];   // [B*T]
    const float* W1 = (const float*)d_in[1];   // [6*32]
    const float* b1 = (const float*)d_in[2];   // [32]
    const float* W2 = (const float*)d_in[3];   // [32*3]
    const float* b2 = (const float*)d_in[4];   // [3]
    float* out = (float*)d_out;                // [B*T*3]

    int B = in_sizes[0] / T_LEN;
    dim3 grid(T_LEN / CTATILE, B);
    gate_router_mma<<<grid, NTHREADS>>>(s, W1, b1, W2, b2, out);
}

// round 16
// speedup vs baseline: 2.5008x; 1.0500x over previous
#include <cuda_runtime.h>
#include <cuda_fp16.h>

// Problem constants (fixed by setup_inputs)
#define T_LEN    131072
#define K_WIN    31
#define HALO     15
#define WTILE    512          // elements per WARP; 4 warps/CTA
#define CTAW     4
#define NTHREADS (32 * CTAW)
#define CTATILE  (WTILE * CTAW)        // 2048 elements per CTA
#define CHUNK    16           // consecutive elements per thread (= one MMA tile)
#define TPITCH   272          // bytes per 16-element tile in feat buffer (17*16)
#define EPS      1e-6f
#define KURT_MAX 20.0f

typedef unsigned long long ull;

// ---- packed f32x2 helpers ---------------------------------------------------
__device__ __forceinline__ ull pack2(float lo, float hi) {
    ull r; asm("mov.b64 %0, {%1, %2};" : "=l"(r) : "f"(lo), "f"(hi)); return r;
}
__device__ __forceinline__ void unpack2(ull a, float &lo, float &hi) {
    asm("mov.b64 {%0, %1}, %2;" : "=f"(lo), "=f"(hi) : "l"(a));
}
__device__ __forceinline__ ull mul2(ull a, ull b) {
    ull d; asm("mul.rn.f32x2 %0, %1, %2;" : "=l"(d) : "l"(a), "l"(b)); return d;
}
__device__ __forceinline__ ull add2(ull a, ull b) {
    ull d; asm("add.rn.f32x2 %0, %1, %2;" : "=l"(d) : "l"(a), "l"(b)); return d;
}
__device__ __forceinline__ ull fma2(ull a, ull b, ull c) {
    ull d; asm("fma.rn.f32x2 %0, %1, %2, %3;" : "=l"(d) : "l"(a), "l"(b), "l"(c));
    return d;
}

// ---- f16 helpers ------------------------------------------------------------
// pack two f32 into f16x2: low half = lo, high half = hi (cvt d,a,b -> hi=a, lo=b)
__device__ __forceinline__ unsigned h2_of(float lo, float hi) {
    unsigned r; asm("cvt.rn.f16x2.f32 %0, %1, %2;" : "=r"(r) : "f"(hi), "f"(lo)); return r;
}
__device__ __forceinline__ unsigned hmax2_zero(unsigned a) {
    unsigned r; asm("max.f16x2 %0, %1, %2;" : "=r"(r) : "r"(a), "r"(0u)); return r;
}

// mma.m16n8k8 f32.f16.f16.f32, C = broadcast zero register (no acc MOV-init)
__device__ __forceinline__ void mma_f16k8_z(float& d0, float& d1, float& d2, float& d3,
                                            unsigned a0, unsigned a1, unsigned b0,
                                            float z) {
    asm volatile("mma.sync.aligned.m16n8k8.row.col.f32.f16.f16.f32 "
                 "{%0,%1,%2,%3}, {%4,%5}, {%6}, {%7,%7,%7,%7};"
                 : "=f"(d0), "=f"(d1), "=f"(d2), "=f"(d3)
                 : "r"(a0), "r"(a1), "r"(b0), "f"(z));
}
// mma.m16n8k16 with explicit C inputs (consumes bias init directly)
__device__ __forceinline__ void mma_f16_c(float& d0, float& d1, float& d2, float& d3,
                                          unsigned a0, unsigned a1, unsigned a2, unsigned a3,
                                          unsigned b0, unsigned b1,
                                          float c0, float c1, float c2, float c3) {
    asm volatile("mma.sync.aligned.m16n8k16.row.col.f32.f16.f16.f32 "
                 "{%0,%1,%2,%3}, {%4,%5,%6,%7}, {%8,%9}, {%10,%11,%12,%13};"
                 : "=f"(d0), "=f"(d1), "=f"(d2), "=f"(d3)
                 : "r"(a0), "r"(a1), "r"(a2), "r"(a3), "r"(b0), "r"(b1),
                   "f"(c0), "f"(c1), "f"(c2), "f"(c3));
}
// mma.m16n8k16 accumulate in place
__device__ __forceinline__ void mma_f16(float& c0, float& c1, float& c2, float& c3,
                                        unsigned a0, unsigned a1, unsigned a2, unsigned a3,
                                        unsigned b0, unsigned b1) {
    asm volatile("mma.sync.aligned.m16n8k16.row.col.f32.f16.f16.f32 "
                 "{%0,%1,%2,%3}, {%4,%5,%6,%7}, {%8,%9}, {%0,%1,%2,%3};"
                 : "+f"(c0), "+f"(c1), "+f"(c2), "+f"(c3)
                 : "r"(a0), "r"(a1), "r"(a2), "r"(a3), "r"(b0), "r"(b1));
}

// 4 warps per CTA; each warp handles its own 512 contiguous elements.
__global__ __launch_bounds__(NTHREADS, 5)
void gate_router_mma(const float* __restrict__ s,
                     const float* __restrict__ W1, const float* __restrict__ b1,
                     const float* __restrict__ W2, const float* __restrict__ b2,
                     float* __restrict__ out)
{
    // Per-warp feature staging: 32 tiles x TPITCH. Tile j's region is reused
    // as f32 logit staging (48 words, output-ordered) after consumption.
    __shared__ __align__(16) unsigned char featb[CTAW * 32 * TPITCH];

    const int tid  = threadIdx.x;
    const int wid  = tid >> 5;
    const int lane = tid & 31;
    const int g  = lane >> 2;       // 0..7  (fragment group = row)
    const int tq = lane & 3;        // 0..3  (thread-in-group)
    const int ctaStart = blockIdx.x * CTATILE;
    const int row = blockIdx.y;
    const float* __restrict__ srow = s + (long long)row * T_LEN;

    // ---- constant fragments (registers; identical derivation per warp) -----
    // GEMM1 B (f16, m16n8k8): b = {W1eff[2tq][n], W1eff[2tq+1][n]}, n = ni*8+g.
    // W1eff rows: 0..5 = W1, 6 = b1 (bias folded; feature 6 == 1.0), 7 = 0.
    unsigned B1[4];
    #pragma unroll
    for (int ni = 0; ni < 4; ++ni) {
        int n = ni * 8 + g;
        int k0 = 2 * tq, k1 = 2 * tq + 1;
        float wlo = (k0 < 6) ? W1[k0 * 32 + n] : b1[n];   // k0 in {0,2,4,6}
        float whi = (k1 < 6) ? W1[k1 * 32 + n] : 0.0f;    // k1 in {1,3,5,7}
        B1[ni] = h2_of(wlo, whi);
    }
    // GEMM2 B (f16, m16n8k16): per kp, b0 = {W2eff[16kp+2tq][g], [+1][g]}, b1 = +8,+9.
    unsigned B2[2][2];
    #pragma unroll
    for (int kp = 0; kp < 2; ++kp) {
        int j0 = kp * 16 + 2 * tq;
        float w00 = (g < 3) ? W2[(j0    ) * 3 + g] : 0.0f;
        float w01 = (g < 3) ? W2[(j0 + 1) * 3 + g] : 0.0f;
        float w10 = (g < 3) ? W2[(j0 + 8) * 3 + g] : 0.0f;
        float w11 = (g < 3) ? W2[(j0 + 9) * 3 + g] : 0.0f;
        B2[kp][0] = h2_of(w00, w01);
        B2[kp][1] = h2_of(w10, w11);
    }
    float cI0 = (2 * tq     < 3) ? b2[2 * tq]     : 0.0f;
    float cI1 = (2 * tq + 1 < 3) ? b2[2 * tq + 1] : 0.0f;
    const float fz = 0.0f;                   // shared zero C-operand

    // ---- thread-private signal window in REGISTERS --------------------------
    // x[i] = srow[t0 - 16 + i], i = 0..47 (covers [t0-16, t0+32), 64B-aligned).
    const int t0 = ctaStart + wid * WTILE + lane * CHUNK;
    float x[48];
    if (t0 >= 16 && t0 + 32 <= T_LEN) {
        const float4* __restrict__ v4 = reinterpret_cast<const float4*>(srow + t0 - 16);
        #pragma unroll
        for (int q = 0; q < 12; ++q) {
            float4 v = v4[q];
            x[4 * q] = v.x; x[4 * q + 1] = v.y; x[4 * q + 2] = v.z; x[4 * q + 3] = v.w;
        }
    } else {
        // boundary threads (2 per row): clamped scalar loads (replicate pad)
        #pragma unroll
        for (int i = 0; i < 48; ++i) {
            int gg = t0 - 16 + i;
            gg = max(0, min(T_LEN - 1, gg));
            x[i] = srow[gg];
        }
    }

    // ---- features: dual sliding chains (elements e and e+8), f32x2-packed --
    unsigned char* warpFeat = featb + wid * 32 * TPITCH;
    unsigned char* myTile = warpFeat + lane * TPITCH;

    const ull INV31p = pack2(1.0f / 31.0f, 1.0f / 31.0f);
    const ull CM1    = pack2(-1.0f, -1.0f);
    const ull CM4    = pack2(-4.0f, -4.0f);
    const ull C6     = pack2( 6.0f,  6.0f);
    const ull CM3    = pack2(-3.0f, -3.0f);
    const ull CEPS   = pack2(EPS, EPS);
    const unsigned ONE_ZERO = 0x00003C00u;    // lo = 1.0h (feature 6), hi = 0

    // init window sums: chainA over x[1..31], chainB over x[9..39]
    ull S1 = 0ull, S2 = 0ull, S3 = 0ull, S4 = 0ull;   // (chainA, chainB)
    #pragma unroll
    for (int k = 0; k < K_WIN; ++k) {
        ull v  = pack2(x[1 + k], x[9 + k]);
        ull v2 = mul2(v, v);
        ull v3 = mul2(v2, v);
        ull v4 = mul2(v2, v2);
        S1 = add2(S1, v);  S2 = add2(S2, v2);
        S3 = add2(S3, v3); S4 = add2(S4, v4);
    }

    // carried diff windows: chainA elem t0 -> xm=x[15], x=x[16]; chainB +8
    float xmA = x[15], xA = x[16];
    float xmB = x[23], xB = x[24];

    #pragma unroll
    for (int p = 0; p < 8; ++p) {
        // packed moments
        ull mu  = mul2(S1, INV31p);
        ull m2  = mul2(S2, INV31p);
        ull m3  = mul2(S3, INV31p);
        ull m4  = mul2(S4, INV31p);
        ull mu2 = mul2(mu, mu);
        ull var = add2(fma2(mu2, CM1, m2), CEPS);
        ull acc = fma2(mul2(mu, m3), CM4, m4);
        acc = fma2(mul2(mu2, m2), C6, acc);
        acc = fma2(mul2(mu2, mu2), CM3, acc);
        ull vv = mul2(var, var);

        float m4cA, m4cB, vvA, vvB, muA, muB, varA, varB;
        unpack2(acc, m4cA, m4cB);
        unpack2(vv,  vvA,  vvB);
        unpack2(mu,  muA,  muB);
        unpack2(var, varA, varB);
        float kurtA = fminf(__fdividef(m4cA, vvA), KURT_MAX);
        float kurtB = fminf(__fdividef(m4cB, vvB), KURT_MAX);

        // diffs from carried window + one fresh register read per chain
        float xpA = x[17 + p];
        float xpB = x[25 + p];
        float d1A = fabsf(xA - xmA);
        float d1B = fabsf(xB - xmB);
        float d2A = fabsf(xpA - 2.0f * xA + xmA);
        float d2B = fabsf(xpB - 2.0f * xB + xmB);
        int tA = t0 + p, tB = t0 + 8 + p;
        if (tA == 0 || tA == T_LEN - 1) d2A = 0.0f;
        if (tB == 0 || tB == T_LEN - 1) d2B = 0.0f;

        // f16 records {x,d1,d2,mu,var,kurt,1,0} -> rows p and p+8 of tile `lane`
        uint4 rA;
        rA.x = h2_of(xA, d1A); rA.y = h2_of(d2A, muA);
        rA.z = h2_of(varA, kurtA); rA.w = ONE_ZERO;
        *reinterpret_cast<uint4*>(myTile + p * 16) = rA;
        uint4 rB;
        rB.x = h2_of(xB, d1B); rB.y = h2_of(d2B, muB);
        rB.z = h2_of(varB, kurtB); rB.w = ONE_ZERO;
        *reinterpret_cast<uint4*>(myTile + (p + 8) * 16) = rB;

        // packed slide: add x[t+16], drop x[t-15] (register indices, const)
        ull xa  = pack2(x[32 + p], x[40 + p]);
        ull xr  = pack2(x[1 + p],  x[9 + p]);
        ull xa2 = mul2(xa, xa), xr2 = mul2(xr, xr);
        S1 = fma2(xr,  CM1, add2(S1, xa));
        S2 = fma2(xr2, CM1, add2(S2, xa2));
        ull xa3 = mul2(xa2, xa), xr3 = mul2(xr2, xr);
        S3 = fma2(xr3, CM1, add2(S3, xa3));
        ull xa4 = mul2(xa2, xa2), xr4 = mul2(xr2, xr2);
        S4 = fma2(xr4, CM1, add2(S4, xa4));

        // advance carried windows
        xmA = xA; xA = xpA;
        xmB = xB; xB = xpB;
    }
    __syncwarp();   // featb tile `lane` visible to warp before A-fragment loads

    // ---- 16 pairs of tiles: two independent GEMM1->relu->GEMM2 chains ------
    #pragma unroll 2
    for (int jp = 0; jp < 16; ++jp) {
        const unsigned char* tbA = warpFeat + (2 * jp) * TPITCH + g * 16 + tq * 4;
        const unsigned char* tbB = tbA + TPITCH;
        unsigned aA0 = *reinterpret_cast<const unsigned*>(tbA);
        unsigned aA1 = *reinterpret_cast<const unsigned*>(tbA + 128);
        unsigned aB0 = *reinterpret_cast<const unsigned*>(tbB);
        unsigned aB1 = *reinterpret_cast<const unsigned*>(tbB + 128);

        float cA0[4], cA1[4], cA2[4], cA3[4];
        float cB0[4], cB1[4], cB2[4], cB3[4];
        #pragma unroll
        for (int ni = 0; ni < 4; ++ni) {
            mma_f16k8_z(cA0[ni], cA1[ni], cA2[ni], cA3[ni], aA0, aA1, B1[ni], fz);
            mma_f16k8_z(cB0[ni], cB1[ni], cB2[ni], cB3[ni], aB0, aB1, B1[ni], fz);
        }

        // relu + pack: C frags == f16 A-frag layout of m16n8k16 (register chain)
        unsigned A2A[2][4], A2B[2][4];
        #pragma unroll
        for (int ni = 0; ni < 4; ++ni) {
            unsigned pA0 = hmax2_zero(h2_of(cA0[ni], cA1[ni]));   // row g
            unsigned pA1 = hmax2_zero(h2_of(cA2[ni], cA3[ni]));   // row g+8
            unsigned pB0 = hmax2_zero(h2_of(cB0[ni], cB1[ni]));
            unsigned pB1 = hmax2_zero(h2_of(cB2[ni], cB3[ni]));
            A2A[ni >> 1][(ni & 1) ? 2 : 0] = pA0;
            A2A[ni >> 1][(ni & 1) ? 3 : 1] = pA1;
            A2B[ni >> 1][(ni & 1) ? 2 : 0] = pB0;
            A2B[ni >> 1][(ni & 1) ? 3 : 1] = pB1;
        }

        float dA0, dA1, dA2, dA3, dB0, dB1, dB2, dB3;
        mma_f16_c(dA0, dA1, dA2, dA3, A2A[0][0], A2A[0][1], A2A[0][2], A2A[0][3],
                  B2[0][0], B2[0][1], cI0, cI1, cI0, cI1);
        mma_f16_c(dB0, dB1, dB2, dB3, A2B[0][0], A2B[0][1], A2B[0][2], A2B[0][3],
                  B2[0][0], B2[0][1], cI0, cI1, cI0, cI1);
        mma_f16(dA0, dA1, dA2, dA3, A2A[1][0], A2A[1][1], A2A[1][2], A2A[1][3], B2[1][0], B2[1][1]);
        mma_f16(dB0, dB1, dB2, dB3, A2B[1][0], A2B[1][1], A2B[1][2], A2B[1][3], B2[1][0], B2[1][1]);

        // WAR-safe without syncwarp: A-loads of both tiles precede the warp-
        // converging mma.sync; these stores depend on GEMM2 results.
        float* tA32 = reinterpret_cast<float*>(warpFeat + (2 * jp) * TPITCH);
        float* tB32 = reinterpret_cast<float*>(warpFeat + (2 * jp + 1) * TPITCH);
        if (tq == 0) {                        // D cols 0,1
            tA32[g * 3]           = dA0;
            tA32[g * 3 + 1]       = dA1;
            tA32[(g + 8) * 3]     = dA2;
            tA32[(g + 8) * 3 + 1] = dA3;
            tB32[g * 3]           = dB0;
            tB32[g * 3 + 1]       = dB1;
            tB32[(g + 8) * 3]     = dB2;
            tB32[(g + 8) * 3 + 1] = dB3;
        } else if (tq == 1) {                 // D col 2 (col 3 = pad)
            tA32[g * 3 + 2]       = dA0;
            tA32[(g + 8) * 3 + 2] = dA2;
            tB32[g * 3 + 2]       = dB0;
            tB32[(g + 8) * 3 + 2] = dB2;
        }
    }
    __syncwarp();

    // ---- coalesced writeout: 1536 floats = 384 float4 per warp -------------
    float* __restrict__ orow = out + ((long long)row * T_LEN + ctaStart + wid * WTILE) * 3;
    float4* __restrict__ o4 = reinterpret_cast<float4*>(orow);
    #pragma unroll
    for (int q = lane; q < 384; q += 32) {
        int j = q / 12;
        int w = q - j * 12;
        o4[q] = *reinterpret_cast<const float4*>(warpFeat + j * TPITCH + w * 16);
    }
}

extern "C" void kernel_launch(void* const* d_in, const int* in_sizes, int n_in,
                              void* d_out, int out_size)
{
    const float* s  = (const float*)d_in[0];   // [B*T]
    const float* W1 = (const float*)d_in[1];   // [6*32]
    const float* b1 = (const float*)d_in[2];   // [32]
    const float* W2 = (const float*)d_in[3];   // [32*3]
    const float* b2 = (const float*)d_in[4];   // [3]
    float* out = (float*)d_out;                // [B*T*3]

    int B = in_sizes[0] / T_LEN;
    dim3 grid(T_LEN / CTATILE, B);
    gate_router_mma<<<grid, NTHREADS>>>(s, W1, b1, W2, b2, out);
}